// round 1
// baseline (speedup 1.0000x reference)
#include <cuda_runtime.h>
#include <math.h>

#define BB 16
#define NN 4096
#define CC 128
#define C2 256
#define NUM_NODES 65536
#define EDGES 2097152

// ---------------- device scratch (static, no allocs) ----------------
static __device__ int   g_is64;
static __device__ int   g_count[NUM_NODES];
static __device__ int   g_off[NUM_NODES + 1];
static __device__ int   g_cursor[NUM_NODES];
static __device__ int   g_src[EDGES];
static __device__ float g_agg[NUM_NODES * CC];
static __device__ float g_sage[NUM_NODES * CC];
static __device__ float g_sum1[CC],  g_ssq1[CC];
static __device__ float g_max1[BB * CC], g_min1[BB * CC];
static __device__ float g_sum2[C2],  g_ssq2[C2];
static __device__ float g_max2[BB * C2], g_min2[BB * C2];

__device__ __forceinline__ float fNINF() { return __int_as_float(0xff800000u); }
__device__ __forceinline__ float fPINF() { return __int_as_float(0x7f800000u); }

__device__ __forceinline__ void atomicMaxF(float* a, float v) {
    if (v >= 0.f) atomicMax((int*)a, __float_as_int(v));
    else          atomicMin((unsigned int*)a, __float_as_uint(v));
}
__device__ __forceinline__ void atomicMinF(float* a, float v) {
    if (v >= 0.f) atomicMin((int*)a, __float_as_int(v));
    else          atomicMax((unsigned int*)a, __float_as_uint(v));
}

// ---------------- dtype sniff: int64 vs int32 topo ----------------
__global__ void k_detect(const unsigned int* __restrict__ topo_u32) {
    if (threadIdx.x == 0 && blockIdx.x == 0) {
        int is64 = 1;
        #pragma unroll 1
        for (int i = 0; i < 32; i++) {
            if (topo_u32[2 * i + 1] != 0u) { is64 = 0; break; }
        }
        g_is64 = is64;
    }
}

// ---------------- init scratch each run (graph-replay safe) ----------------
__global__ void k_init() {
    int i = blockIdx.x * blockDim.x + threadIdx.x;
    if (i < NUM_NODES) g_count[i] = 0;
    if (i < CC) { g_sum1[i] = 0.f; g_ssq1[i] = 0.f; }
    if (i < C2) { g_sum2[i] = 0.f; g_ssq2[i] = 0.f; }
    if (i < BB * CC) { g_max1[i] = fNINF(); g_min1[i] = fPINF(); }
    if (i < BB * C2) { g_max2[i] = fNINF(); g_min2[i] = fPINF(); }
}

// ---------------- CSR build ----------------
__global__ void k_hist(const void* __restrict__ topo) {
    int e = blockIdx.x * blockDim.x + threadIdx.x;
    if (e >= EDGES) return;
    int d = g_is64 ? (int)((const long long*)topo)[EDGES + e]
                   : ((const int*)topo)[EDGES + e];
    atomicAdd(&g_count[d], 1);
}

__global__ void k_scan() {
    __shared__ int sh[1024];
    int t = threadIdx.x;
    int base = t * 64;
    int s = 0;
    #pragma unroll 1
    for (int i = 0; i < 64; i++) s += g_count[base + i];
    sh[t] = s;
    __syncthreads();
    for (int ofs = 1; ofs < 1024; ofs <<= 1) {
        int v = (t >= ofs) ? sh[t - ofs] : 0;
        __syncthreads();
        sh[t] += v;
        __syncthreads();
    }
    int run = sh[t] - s;  // exclusive prefix
    #pragma unroll 1
    for (int i = 0; i < 64; i++) {
        int c = g_count[base + i];
        g_off[base + i] = run;
        g_cursor[base + i] = run;
        run += c;
    }
    if (t == 1023) g_off[NUM_NODES] = run;
}

__global__ void k_scatter(const void* __restrict__ topo) {
    int e = blockIdx.x * blockDim.x + threadIdx.x;
    if (e >= EDGES) return;
    int s, d;
    if (g_is64) {
        s = (int)((const long long*)topo)[e];
        d = (int)((const long long*)topo)[EDGES + e];
    } else {
        s = ((const int*)topo)[e];
        d = ((const int*)topo)[EDGES + e];
    }
    int pos = atomicAdd(&g_cursor[d], 1);
    g_src[pos] = s;
}

// ---------------- per-node max aggregation (warp per node) ----------------
__global__ __launch_bounds__(256) void k_agg(const float* __restrict__ feat) {
    int gwarp = (blockIdx.x * blockDim.x + threadIdx.x) >> 5;
    int lane = threadIdx.x & 31;
    if (gwarp >= NUM_NODES) return;
    int beg = g_off[gwarp], end = g_off[gwarp + 1];
    float4 acc = make_float4(fNINF(), fNINF(), fNINF(), fNINF());
    int i = beg;
    for (; i + 2 <= end; i += 2) {
        int s0 = g_src[i], s1 = g_src[i + 1];
        float4 v0 = ((const float4*)(feat + (size_t)s0 * CC))[lane];
        float4 v1 = ((const float4*)(feat + (size_t)s1 * CC))[lane];
        acc.x = fmaxf(acc.x, fmaxf(v0.x, v1.x));
        acc.y = fmaxf(acc.y, fmaxf(v0.y, v1.y));
        acc.z = fmaxf(acc.z, fmaxf(v0.z, v1.z));
        acc.w = fmaxf(acc.w, fmaxf(v0.w, v1.w));
    }
    if (i < end) {
        int s0 = g_src[i];
        float4 v0 = ((const float4*)(feat + (size_t)s0 * CC))[lane];
        acc.x = fmaxf(acc.x, v0.x);
        acc.y = fmaxf(acc.y, v0.y);
        acc.z = fmaxf(acc.z, v0.z);
        acc.w = fmaxf(acc.w, v0.w);
    }
    if (beg == end) acc = make_float4(0.f, 0.f, 0.f, 0.f);  // empty segment -> 0
    ((float4*)(g_agg + (size_t)gwarp * CC))[lane] = acc;
}

// ---------------- sage = agg@Wl^T + b + feat@Wr^T, then row L2-normalize ----------------
#define RPB 64
#define PW 132
#define PA 68
__global__ __launch_bounds__(256) void k_sage(const float* __restrict__ feat,
                                              const float* __restrict__ Wl,
                                              const float* __restrict__ bl,
                                              const float* __restrict__ Wr) {
    extern __shared__ float sm[];
    float* shWl = sm;                     // [k][n] padded PW
    float* shWr = shWl + CC * PW;
    float* shA  = shWr + CC * PW;         // [k][r] padded PA
    float* shF  = shA + CC * PA;

    int tid = threadIdx.x;
    int lane = tid & 31, ws = tid >> 5;
    int row0 = blockIdx.x * RPB;

    for (int idx = tid; idx < CC * CC; idx += 256) {
        int k = idx & (CC - 1), n = idx >> 7;
        shWl[k * PW + n] = Wl[idx];   // Wl is [n][k], idx=n*128+k (coalesced)
        shWr[k * PW + n] = Wr[idx];
    }
    for (int idx = tid; idx < RPB * CC; idx += 256) {
        int k = idx & (CC - 1), r = idx >> 7;
        shA[k * PA + r] = g_agg[(row0 + r) * CC + k];
        shF[k * PA + r] = feat[(size_t)(row0 + r) * CC + k];
    }
    __syncthreads();

    float acc0[8], acc1[8], acc2[8], acc3[8];
    #pragma unroll
    for (int r = 0; r < 8; r++) { acc0[r] = 0; acc1[r] = 0; acc2[r] = 0; acc3[r] = 0; }

    #pragma unroll 4
    for (int k = 0; k < CC; k++) {
        float4 wl = *(const float4*)&shWl[k * PW + 4 * lane];
        float4 wr = *(const float4*)&shWr[k * PW + 4 * lane];
        float4 a0 = *(const float4*)&shA[k * PA + 8 * ws];
        float4 a1 = *(const float4*)&shA[k * PA + 8 * ws + 4];
        float4 f0 = *(const float4*)&shF[k * PA + 8 * ws];
        float4 f1 = *(const float4*)&shF[k * PA + 8 * ws + 4];
        float av[8] = {a0.x, a0.y, a0.z, a0.w, a1.x, a1.y, a1.z, a1.w};
        float fv[8] = {f0.x, f0.y, f0.z, f0.w, f1.x, f1.y, f1.z, f1.w};
        #pragma unroll
        for (int r = 0; r < 8; r++) {
            acc0[r] = fmaf(wl.x, av[r], fmaf(wr.x, fv[r], acc0[r]));
            acc1[r] = fmaf(wl.y, av[r], fmaf(wr.y, fv[r], acc1[r]));
            acc2[r] = fmaf(wl.z, av[r], fmaf(wr.z, fv[r], acc2[r]));
            acc3[r] = fmaf(wl.w, av[r], fmaf(wr.w, fv[r], acc3[r]));
        }
    }

    float b0 = bl[4 * lane], b1 = bl[4 * lane + 1], b2 = bl[4 * lane + 2], b3 = bl[4 * lane + 3];
    #pragma unroll
    for (int r = 0; r < 8; r++) {
        float v0 = acc0[r] + b0, v1 = acc1[r] + b1, v2 = acc2[r] + b2, v3 = acc3[r] + b3;
        float ss = v0 * v0 + v1 * v1 + v2 * v2 + v3 * v3;
        #pragma unroll
        for (int o = 16; o > 0; o >>= 1) ss += __shfl_xor_sync(0xffffffffu, ss, o);
        float inv = 1.f / fmaxf(sqrtf(ss), 1e-12f);
        float4 o4 = make_float4(v0 * inv, v1 * inv, v2 * inv, v3 * inv);
        *(float4*)&g_sage[(row0 + 8 * ws + r) * CC + 4 * lane] = o4;
    }
}

// ---------------- fused conv1(k=3) + stats (sum/sumsq global, max/min per graph) ----------------
#define L1T 128
#define PL1 131
#define CI1 64
__global__ __launch_bounds__(256) void k_conv1(const float* __restrict__ w1,
                                               const float* __restrict__ b1) {
    extern __shared__ float sm[];
    float* shX = sm;                 // [ci][l] padded PL1, (L1T+2) rows
    float* shW = sm + CC * PL1;      // [(ci*3+k)][co]
    int tid = threadIdx.x;
    int lane = tid & 31, ws = tid >> 5;
    int b = blockIdx.y;
    int l0 = blockIdx.x * L1T;
    int nrows = NN - l0; if (nrows > L1T + 2) nrows = L1T + 2;

    for (int idx = tid; idx < (L1T + 2) * CC; idx += 256) {
        int l = idx >> 7, ci = idx & (CC - 1);
        shX[ci * PL1 + l] = (l < nrows) ? g_sage[(b * NN + l0 + l) * CC + ci] : 0.f;
    }

    float acc0[16], acc1[16], acc2[16], acc3[16];
    #pragma unroll
    for (int l = 0; l < 16; l++) { acc0[l] = 0; acc1[l] = 0; acc2[l] = 0; acc3[l] = 0; }

    for (int cc0 = 0; cc0 < CC; cc0 += CI1) {
        __syncthreads();
        for (int idx = tid; idx < CI1 * 3 * CC; idx += 256) {
            int co = idx & (CC - 1); int rem = idx >> 7;  // rem = ci*3+k
            shW[rem * CC + co] = w1[co * (CC * 3) + cc0 * 3 + rem];
        }
        __syncthreads();
        #pragma unroll 2
        for (int ci = 0; ci < CI1; ci++) {
            float x[18];
            int base = (cc0 + ci) * PL1 + 16 * ws;
            #pragma unroll
            for (int i = 0; i < 18; i++) x[i] = shX[base + i];
            #pragma unroll
            for (int k = 0; k < 3; k++) {
                float4 w = *(const float4*)&shW[(ci * 3 + k) * CC + 4 * lane];
                #pragma unroll
                for (int l = 0; l < 16; l++) {
                    float xv = x[l + k];
                    acc0[l] = fmaf(w.x, xv, acc0[l]);
                    acc1[l] = fmaf(w.y, xv, acc1[l]);
                    acc2[l] = fmaf(w.z, xv, acc2[l]);
                    acc3[l] = fmaf(w.w, xv, acc3[l]);
                }
            }
        }
    }

    int co0 = 4 * lane;
    float bb[4] = {b1[co0], b1[co0 + 1], b1[co0 + 2], b1[co0 + 3]};
    float mmax[4], mmin[4], msum[4], mssq[4];
    #pragma unroll
    for (int j = 0; j < 4; j++) { mmax[j] = fNINF(); mmin[j] = fPINF(); msum[j] = 0; mssq[j] = 0; }
    int lbase = l0 + 16 * ws;
    #pragma unroll
    for (int l = 0; l < 16; l++) {
        if (lbase + l <= NN - 3) {
            float v[4] = {acc0[l] + bb[0], acc1[l] + bb[1], acc2[l] + bb[2], acc3[l] + bb[3]};
            #pragma unroll
            for (int j = 0; j < 4; j++) {
                mmax[j] = fmaxf(mmax[j], v[j]);
                mmin[j] = fminf(mmin[j], v[j]);
                msum[j] += v[j];
                mssq[j] += v[j] * v[j];
            }
        }
    }
    #pragma unroll
    for (int j = 0; j < 4; j++) {
        int co = co0 + j;
        atomicAdd(&g_sum1[co], msum[j]);
        atomicAdd(&g_ssq1[co], mssq[j]);
        atomicMaxF(&g_max1[b * CC + co], mmax[j]);
        atomicMinF(&g_min1[b * CC + co], mmin[j]);
    }
}

// ---------------- fused conv2 (2C channels, input = concat(sage, feature)) ----------------
#define L2T 64
#define PL2 67
#define CI2 32
__global__ __launch_bounds__(256) void k_conv2(const float* __restrict__ feat,
                                               const float* __restrict__ w2,
                                               const float* __restrict__ b2) {
    extern __shared__ float sm[];
    float* shX = sm;                 // [ci][l] padded PL2, 66 rows, ci<256
    float* shW = sm + C2 * PL2;      // [(ci*3+k)][co]
    int tid = threadIdx.x;
    int coq = tid & 63, ws = tid >> 6;   // 64 co-quads, 4 l-slots x 16
    int b = blockIdx.y;
    int l0 = blockIdx.x * L2T;
    int nrows = NN - l0; if (nrows > L2T + 2) nrows = L2T + 2;

    for (int idx = tid; idx < (L2T + 2) * C2; idx += 256) {
        int l = idx >> 8, ci = idx & (C2 - 1);
        float v = 0.f;
        if (l < nrows) {
            int row = b * NN + l0 + l;
            v = (ci < CC) ? g_sage[row * CC + ci] : feat[(size_t)row * CC + (ci - CC)];
        }
        shX[ci * PL2 + l] = v;
    }

    float acc0[16], acc1[16], acc2[16], acc3[16];
    #pragma unroll
    for (int l = 0; l < 16; l++) { acc0[l] = 0; acc1[l] = 0; acc2[l] = 0; acc3[l] = 0; }

    for (int cc0 = 0; cc0 < C2; cc0 += CI2) {
        __syncthreads();
        for (int idx = tid; idx < CI2 * 3 * C2; idx += 256) {
            int co = idx & (C2 - 1); int rem = idx >> 8;   // rem = ci*3+k
            shW[rem * C2 + co] = w2[co * (C2 * 3) + cc0 * 3 + rem];
        }
        __syncthreads();
        #pragma unroll 2
        for (int ci = 0; ci < CI2; ci++) {
            float x[18];
            int base = (cc0 + ci) * PL2 + 16 * ws;
            #pragma unroll
            for (int i = 0; i < 18; i++) x[i] = shX[base + i];
            #pragma unroll
            for (int k = 0; k < 3; k++) {
                float4 w = *(const float4*)&shW[(ci * 3 + k) * C2 + 4 * coq];
                #pragma unroll
                for (int l = 0; l < 16; l++) {
                    float xv = x[l + k];
                    acc0[l] = fmaf(w.x, xv, acc0[l]);
                    acc1[l] = fmaf(w.y, xv, acc1[l]);
                    acc2[l] = fmaf(w.z, xv, acc2[l]);
                    acc3[l] = fmaf(w.w, xv, acc3[l]);
                }
            }
        }
    }

    int co0 = 4 * coq;
    float bb[4] = {b2[co0], b2[co0 + 1], b2[co0 + 2], b2[co0 + 3]};
    float mmax[4], mmin[4], msum[4], mssq[4];
    #pragma unroll
    for (int j = 0; j < 4; j++) { mmax[j] = fNINF(); mmin[j] = fPINF(); msum[j] = 0; mssq[j] = 0; }
    int lbase = l0 + 16 * ws;
    #pragma unroll
    for (int l = 0; l < 16; l++) {
        if (lbase + l <= NN - 3) {
            float v[4] = {acc0[l] + bb[0], acc1[l] + bb[1], acc2[l] + bb[2], acc3[l] + bb[3]};
            #pragma unroll
            for (int j = 0; j < 4; j++) {
                mmax[j] = fmaxf(mmax[j], v[j]);
                mmin[j] = fminf(mmin[j], v[j]);
                msum[j] += v[j];
                mssq[j] += v[j] * v[j];
            }
        }
    }
    #pragma unroll
    for (int j = 0; j < 4; j++) {
        int co = co0 + j;
        atomicAdd(&g_sum2[co], msum[j]);
        atomicAdd(&g_ssq2[co], mssq[j]);
        atomicMaxF(&g_max2[b * C2 + co], mmax[j]);
        atomicMinF(&g_min2[b * C2 + co], mmin[j]);
    }
}

// ---------------- finish: BN affine + relu + pool + linears + product ----------------
__global__ __launch_bounds__(512) void k_final(const float* __restrict__ g1, const float* __restrict__ be1,
                                               const float* __restrict__ g2, const float* __restrict__ be2,
                                               const float* __restrict__ l1w, const float* __restrict__ l1b,
                                               const float* __restrict__ l2w, const float* __restrict__ l2b,
                                               float* __restrict__ out) {
    __shared__ float p1[BB * CC];
    __shared__ float p2[BB * C2];
    int tid = threadIdx.x;
    const float cnt = (float)(BB * (NN - 2));

    for (int c = tid; c < CC; c += 512) {
        float m = g_sum1[c] / cnt;
        float v = g_ssq1[c] / cnt - m * m;
        float a = g1[c] * rsqrtf(fmaxf(v, 0.f) + 1e-5f);
        float o = be1[c] - a * m;
        for (int b = 0; b < BB; b++) {
            float x = (a >= 0.f) ? g_max1[b * CC + c] : g_min1[b * CC + c];
            p1[b * CC + c] = fmaxf(a * x + o, 0.f);
        }
    }
    for (int c = tid; c < C2; c += 512) {
        float m = g_sum2[c] / cnt;
        float v = g_ssq2[c] / cnt - m * m;
        float a = g2[c] * rsqrtf(fmaxf(v, 0.f) + 1e-5f);
        float o = be2[c] - a * m;
        for (int b = 0; b < BB; b++) {
            float x = (a >= 0.f) ? g_max2[b * C2 + c] : g_min2[b * C2 + c];
            p2[b * C2 + c] = fmaxf(a * x + o, 0.f);
        }
    }
    __syncthreads();
    if (tid < 32) {
        int b = tid >> 1, j = tid & 1;
        float s1 = l1b[j];
        for (int c = 0; c < CC; c++) s1 += p1[b * CC + c] * l1w[j * CC + c];
        float s2 = l2b[j];
        for (int c = 0; c < C2; c++) s2 += p2[b * C2 + c] * l2w[j * C2 + c];
        out[tid] = s1 * s2;
    }
}

// ---------------- host ----------------
extern "C" void kernel_launch(void* const* d_in, const int* in_sizes, int n_in,
                              void* d_out, int out_size) {
    const float* feature = (const float*)d_in[0];
    const void*  topo    = d_in[1];
    const float* lin_l_w = (const float*)d_in[3];
    const float* lin_l_b = (const float*)d_in[4];
    const float* lin_r_w = (const float*)d_in[5];
    const float* conv1_w = (const float*)d_in[6];
    const float* conv1_b = (const float*)d_in[7];
    const float* bn1_g   = (const float*)d_in[8];
    const float* bn1_b   = (const float*)d_in[9];
    const float* conv2_w = (const float*)d_in[10];
    const float* conv2_b = (const float*)d_in[11];
    const float* bn2_g   = (const float*)d_in[12];
    const float* bn2_b   = (const float*)d_in[13];
    const float* lin1_w  = (const float*)d_in[14];
    const float* lin1_b  = (const float*)d_in[15];
    const float* lin2_w  = (const float*)d_in[16];
    const float* lin2_b  = (const float*)d_in[17];
    float* out = (float*)d_out;

    const int SM_SAGE  = (CC * PW * 2 + CC * PA * 2) * 4;          // 204800 B
    const int SM_CONV1 = (CC * PL1 + CI1 * 3 * CC) * 4;            // 165376 B
    const int SM_CONV2 = (C2 * PL2 + CI2 * 3 * C2) * 4;            // 166912 B
    cudaFuncSetAttribute(k_sage,  cudaFuncAttributeMaxDynamicSharedMemorySize, SM_SAGE);
    cudaFuncSetAttribute(k_conv1, cudaFuncAttributeMaxDynamicSharedMemorySize, SM_CONV1);
    cudaFuncSetAttribute(k_conv2, cudaFuncAttributeMaxDynamicSharedMemorySize, SM_CONV2);

    k_detect<<<1, 32>>>((const unsigned int*)topo);
    k_init<<<256, 256>>>();
    k_hist<<<EDGES / 256, 256>>>(topo);
    k_scan<<<1, 1024>>>();
    k_scatter<<<EDGES / 256, 256>>>(topo);
    k_agg<<<NUM_NODES / 8, 256>>>(feature);
    k_sage<<<NUM_NODES / RPB, 256, SM_SAGE>>>(feature, lin_l_w, lin_l_b, lin_r_w);
    k_conv1<<<dim3(NN / L1T, BB), 256, SM_CONV1>>>(conv1_w, conv1_b);
    k_conv2<<<dim3(NN / L2T, BB), 256, SM_CONV2>>>(feature, conv2_w, conv2_b);
    k_final<<<1, 512>>>(bn1_g, bn1_b, bn2_g, bn2_b,
                        lin1_w, lin1_b, lin2_w, lin2_b, out);
}

// round 2
// speedup vs baseline: 1.0467x; 1.0467x over previous
#include <cuda_runtime.h>
#include <math.h>

#define BB 16
#define NN 4096
#define CC 128
#define C2 256
#define NUM_NODES 65536
#define EDGES 2097152

// ---------------- device scratch (static, no allocs) ----------------
static __device__ int   g_is64;
static __device__ int   g_count[NUM_NODES];
static __device__ int   g_off[NUM_NODES + 1];
static __device__ int   g_cursor[NUM_NODES];
static __device__ int   g_blksum[256];
static __device__ int   g_src[EDGES];
static __device__ float g_agg[NUM_NODES * CC];
static __device__ float g_sage[NUM_NODES * CC];
static __device__ float g_sum1[CC],  g_ssq1[CC];
static __device__ float g_max1[BB * CC], g_min1[BB * CC];
static __device__ float g_sum2[C2],  g_ssq2[C2];
static __device__ float g_max2[BB * C2], g_min2[BB * C2];

__device__ __forceinline__ float fNINF() { return __int_as_float(0xff800000u); }
__device__ __forceinline__ float fPINF() { return __int_as_float(0x7f800000u); }

__device__ __forceinline__ void atomicMaxF(float* a, float v) {
    if (v >= 0.f) atomicMax((int*)a, __float_as_int(v));
    else          atomicMin((unsigned int*)a, __float_as_uint(v));
}
__device__ __forceinline__ void atomicMinF(float* a, float v) {
    if (v >= 0.f) atomicMin((int*)a, __float_as_int(v));
    else          atomicMax((unsigned int*)a, __float_as_uint(v));
}

// ---------------- dtype sniff: int64 vs int32 topo ----------------
__global__ void k_detect(const unsigned int* __restrict__ topo_u32) {
    if (threadIdx.x == 0 && blockIdx.x == 0) {
        int is64 = 1;
        #pragma unroll 1
        for (int i = 0; i < 32; i++) {
            if (topo_u32[2 * i + 1] != 0u) { is64 = 0; break; }
        }
        g_is64 = is64;
    }
}

// ---------------- init scratch each run (graph-replay safe) ----------------
__global__ void k_init() {
    int i = blockIdx.x * blockDim.x + threadIdx.x;
    if (i < NUM_NODES) g_count[i] = 0;
    if (i < CC) { g_sum1[i] = 0.f; g_ssq1[i] = 0.f; }
    if (i < C2) { g_sum2[i] = 0.f; g_ssq2[i] = 0.f; }
    if (i < BB * CC) { g_max1[i] = fNINF(); g_min1[i] = fPINF(); }
    if (i < BB * C2) { g_max2[i] = fNINF(); g_min2[i] = fPINF(); }
}

// ---------------- CSR build ----------------
__global__ void k_hist(const void* __restrict__ topo) {
    int e = blockIdx.x * blockDim.x + threadIdx.x;
    if (e >= EDGES) return;
    int d = g_is64 ? (int)((const long long*)topo)[EDGES + e]
                   : ((const int*)topo)[EDGES + e];
    atomicAdd(&g_count[d], 1);
}

// 3-phase multi-block scan of g_count -> g_off/g_cursor
__global__ void k_scan1() {
    __shared__ int sh[256];
    int b = blockIdx.x, t = threadIdx.x;
    int i = b * 256 + t;
    int c = g_count[i];
    sh[t] = c;
    __syncthreads();
    for (int ofs = 1; ofs < 256; ofs <<= 1) {
        int v = (t >= ofs) ? sh[t - ofs] : 0;
        __syncthreads();
        sh[t] += v;
        __syncthreads();
    }
    g_off[i] = sh[t] - c;          // block-relative exclusive prefix
    if (t == 255) g_blksum[b] = sh[255];
}

__global__ void k_scan2() {
    __shared__ int sh[256];
    int t = threadIdx.x;
    int c = g_blksum[t];
    sh[t] = c;
    __syncthreads();
    for (int ofs = 1; ofs < 256; ofs <<= 1) {
        int v = (t >= ofs) ? sh[t - ofs] : 0;
        __syncthreads();
        sh[t] += v;
        __syncthreads();
    }
    g_blksum[t] = sh[t] - c;       // exclusive block offsets
}

__global__ void k_scan3() {
    int b = blockIdx.x, t = threadIdx.x;
    int i = b * 256 + t;
    int v = g_off[i] + g_blksum[b];
    g_off[i] = v;
    g_cursor[i] = v;
    if (i == NUM_NODES - 1) g_off[NUM_NODES] = EDGES;
}

__global__ void k_scatter(const void* __restrict__ topo) {
    int e = blockIdx.x * blockDim.x + threadIdx.x;
    if (e >= EDGES) return;
    int s, d;
    if (g_is64) {
        s = (int)((const long long*)topo)[e];
        d = (int)((const long long*)topo)[EDGES + e];
    } else {
        s = ((const int*)topo)[e];
        d = ((const int*)topo)[EDGES + e];
    }
    int pos = atomicAdd(&g_cursor[d], 1);
    g_src[pos] = s;
}

// ---------------- per-node max aggregation (warp per node, 4-edge MLP) ----------------
__global__ __launch_bounds__(256) void k_agg(const float* __restrict__ feat) {
    int gwarp = (blockIdx.x * blockDim.x + threadIdx.x) >> 5;
    int lane = threadIdx.x & 31;
    if (gwarp >= NUM_NODES) return;
    int beg = g_off[gwarp], end = g_off[gwarp + 1];
    float4 acc = make_float4(fNINF(), fNINF(), fNINF(), fNINF());
    int i = beg;
    for (; i + 4 <= end; i += 4) {
        int s0 = g_src[i], s1 = g_src[i + 1], s2 = g_src[i + 2], s3 = g_src[i + 3];
        float4 v0 = __ldg(((const float4*)(feat + (size_t)s0 * CC)) + lane);
        float4 v1 = __ldg(((const float4*)(feat + (size_t)s1 * CC)) + lane);
        float4 v2 = __ldg(((const float4*)(feat + (size_t)s2 * CC)) + lane);
        float4 v3 = __ldg(((const float4*)(feat + (size_t)s3 * CC)) + lane);
        float mx = fmaxf(fmaxf(v0.x, v1.x), fmaxf(v2.x, v3.x));
        float my = fmaxf(fmaxf(v0.y, v1.y), fmaxf(v2.y, v3.y));
        float mz = fmaxf(fmaxf(v0.z, v1.z), fmaxf(v2.z, v3.z));
        float mw = fmaxf(fmaxf(v0.w, v1.w), fmaxf(v2.w, v3.w));
        acc.x = fmaxf(acc.x, mx);
        acc.y = fmaxf(acc.y, my);
        acc.z = fmaxf(acc.z, mz);
        acc.w = fmaxf(acc.w, mw);
    }
    for (; i < end; i++) {
        int s0 = g_src[i];
        float4 v0 = __ldg(((const float4*)(feat + (size_t)s0 * CC)) + lane);
        acc.x = fmaxf(acc.x, v0.x);
        acc.y = fmaxf(acc.y, v0.y);
        acc.z = fmaxf(acc.z, v0.z);
        acc.w = fmaxf(acc.w, v0.w);
    }
    if (beg == end) acc = make_float4(0.f, 0.f, 0.f, 0.f);  // empty segment -> 0
    ((float4*)(g_agg + (size_t)gwarp * CC))[lane] = acc;
}

// ---------------- sage = agg@Wl^T + b + feat@Wr^T, then row L2-normalize ----------------
#define RPB 64
#define PW 132
#define PA 68
__global__ __launch_bounds__(256) void k_sage(const float* __restrict__ feat,
                                              const float* __restrict__ Wl,
                                              const float* __restrict__ bl,
                                              const float* __restrict__ Wr) {
    extern __shared__ float sm[];
    float* shWl = sm;                     // [k][n] padded PW
    float* shWr = shWl + CC * PW;
    float* shA  = shWr + CC * PW;         // [k][r] padded PA
    float* shF  = shA + CC * PA;

    int tid = threadIdx.x;
    int lane = tid & 31, ws = tid >> 5;
    int row0 = blockIdx.x * RPB;

    for (int idx = tid; idx < CC * CC; idx += 256) {
        int k = idx & (CC - 1), n = idx >> 7;
        shWl[k * PW + n] = Wl[idx];   // Wl is [n][k], idx=n*128+k (coalesced)
        shWr[k * PW + n] = Wr[idx];
    }
    for (int idx = tid; idx < RPB * CC; idx += 256) {
        int k = idx & (CC - 1), r = idx >> 7;
        shA[k * PA + r] = g_agg[(row0 + r) * CC + k];
        shF[k * PA + r] = feat[(size_t)(row0 + r) * CC + k];
    }
    __syncthreads();

    float acc0[8], acc1[8], acc2[8], acc3[8];
    #pragma unroll
    for (int r = 0; r < 8; r++) { acc0[r] = 0; acc1[r] = 0; acc2[r] = 0; acc3[r] = 0; }

    #pragma unroll 4
    for (int k = 0; k < CC; k++) {
        float4 wl = *(const float4*)&shWl[k * PW + 4 * lane];
        float4 wr = *(const float4*)&shWr[k * PW + 4 * lane];
        float4 a0 = *(const float4*)&shA[k * PA + 8 * ws];
        float4 a1 = *(const float4*)&shA[k * PA + 8 * ws + 4];
        float4 f0 = *(const float4*)&shF[k * PA + 8 * ws];
        float4 f1 = *(const float4*)&shF[k * PA + 8 * ws + 4];
        float av[8] = {a0.x, a0.y, a0.z, a0.w, a1.x, a1.y, a1.z, a1.w};
        float fv[8] = {f0.x, f0.y, f0.z, f0.w, f1.x, f1.y, f1.z, f1.w};
        #pragma unroll
        for (int r = 0; r < 8; r++) {
            acc0[r] = fmaf(wl.x, av[r], fmaf(wr.x, fv[r], acc0[r]));
            acc1[r] = fmaf(wl.y, av[r], fmaf(wr.y, fv[r], acc1[r]));
            acc2[r] = fmaf(wl.z, av[r], fmaf(wr.z, fv[r], acc2[r]));
            acc3[r] = fmaf(wl.w, av[r], fmaf(wr.w, fv[r], acc3[r]));
        }
    }

    float b0 = bl[4 * lane], b1 = bl[4 * lane + 1], b2 = bl[4 * lane + 2], b3 = bl[4 * lane + 3];
    #pragma unroll
    for (int r = 0; r < 8; r++) {
        float v0 = acc0[r] + b0, v1 = acc1[r] + b1, v2 = acc2[r] + b2, v3 = acc3[r] + b3;
        float ss = v0 * v0 + v1 * v1 + v2 * v2 + v3 * v3;
        #pragma unroll
        for (int o = 16; o > 0; o >>= 1) ss += __shfl_xor_sync(0xffffffffu, ss, o);
        float inv = 1.f / fmaxf(sqrtf(ss), 1e-12f);
        float4 o4 = make_float4(v0 * inv, v1 * inv, v2 * inv, v3 * inv);
        *(float4*)&g_sage[(row0 + 8 * ws + r) * CC + 4 * lane] = o4;
    }
}

// ---------------- fused conv1(k=3) + stats, 512 threads ----------------
#define L1T 128
#define PL1 131
#define CI1 64
__global__ __launch_bounds__(512) void k_conv1(const float* __restrict__ w1,
                                               const float* __restrict__ b1) {
    extern __shared__ float sm[];
    float* shX = sm;                 // [ci][l] padded PL1, (L1T+2) rows
    float* shW = sm + CC * PL1;      // [(ci*3+k)][co]
    int tid = threadIdx.x;
    int coq = tid & 31, ws = tid >> 5;   // 32 co-quads, 16 l-slots x 8
    int b = blockIdx.y;
    int l0 = blockIdx.x * L1T;
    int nrows = NN - l0; if (nrows > L1T + 2) nrows = L1T + 2;

    for (int idx = tid; idx < (L1T + 2) * CC; idx += 512) {
        int l = idx >> 7, ci = idx & (CC - 1);
        shX[ci * PL1 + l] = (l < nrows) ? g_sage[(b * NN + l0 + l) * CC + ci] : 0.f;
    }

    float acc0[8], acc1[8], acc2[8], acc3[8];
    #pragma unroll
    for (int l = 0; l < 8; l++) { acc0[l] = 0; acc1[l] = 0; acc2[l] = 0; acc3[l] = 0; }

    for (int cc0 = 0; cc0 < CC; cc0 += CI1) {
        __syncthreads();
        for (int idx = tid; idx < CI1 * 3 * CC; idx += 512) {
            int co = idx & (CC - 1); int rem = idx >> 7;  // rem = ci*3+k
            shW[rem * CC + co] = w1[co * (CC * 3) + cc0 * 3 + rem];
        }
        __syncthreads();
        #pragma unroll 2
        for (int ci = 0; ci < CI1; ci++) {
            float x[10];
            int base = (cc0 + ci) * PL1 + 8 * ws;
            #pragma unroll
            for (int i = 0; i < 10; i++) x[i] = shX[base + i];
            #pragma unroll
            for (int k = 0; k < 3; k++) {
                float4 w = *(const float4*)&shW[(ci * 3 + k) * CC + 4 * coq];
                #pragma unroll
                for (int l = 0; l < 8; l++) {
                    float xv = x[l + k];
                    acc0[l] = fmaf(w.x, xv, acc0[l]);
                    acc1[l] = fmaf(w.y, xv, acc1[l]);
                    acc2[l] = fmaf(w.z, xv, acc2[l]);
                    acc3[l] = fmaf(w.w, xv, acc3[l]);
                }
            }
        }
    }

    int co0 = 4 * coq;
    float bb[4] = {b1[co0], b1[co0 + 1], b1[co0 + 2], b1[co0 + 3]};
    float mmax[4], mmin[4], msum[4], mssq[4];
    #pragma unroll
    for (int j = 0; j < 4; j++) { mmax[j] = fNINF(); mmin[j] = fPINF(); msum[j] = 0; mssq[j] = 0; }
    int lbase = l0 + 8 * ws;
    #pragma unroll
    for (int l = 0; l < 8; l++) {
        if (lbase + l <= NN - 3) {
            float v[4] = {acc0[l] + bb[0], acc1[l] + bb[1], acc2[l] + bb[2], acc3[l] + bb[3]};
            #pragma unroll
            for (int j = 0; j < 4; j++) {
                mmax[j] = fmaxf(mmax[j], v[j]);
                mmin[j] = fminf(mmin[j], v[j]);
                msum[j] += v[j];
                mssq[j] += v[j] * v[j];
            }
        }
    }
    #pragma unroll
    for (int j = 0; j < 4; j++) {
        int co = co0 + j;
        atomicAdd(&g_sum1[co], msum[j]);
        atomicAdd(&g_ssq1[co], mssq[j]);
        atomicMaxF(&g_max1[b * CC + co], mmax[j]);
        atomicMinF(&g_min1[b * CC + co], mmin[j]);
    }
}

// ---------------- fused conv2 (2C channels, input = concat(sage, feature)), 512 threads ----------------
#define L2T 64
#define PL2 67
#define CI2 32
__global__ __launch_bounds__(512) void k_conv2(const float* __restrict__ feat,
                                               const float* __restrict__ w2,
                                               const float* __restrict__ b2) {
    extern __shared__ float sm[];
    float* shX = sm;                 // [ci][l] padded PL2, 66 rows, ci<256
    float* shW = sm + C2 * PL2;      // [(ci*3+k)][co]
    int tid = threadIdx.x;
    int coq = tid & 63, ws = tid >> 6;   // 64 co-quads, 8 l-slots x 8
    int b = blockIdx.y;
    int l0 = blockIdx.x * L2T;
    int nrows = NN - l0; if (nrows > L2T + 2) nrows = L2T + 2;

    for (int idx = tid; idx < (L2T + 2) * C2; idx += 512) {
        int l = idx >> 8, ci = idx & (C2 - 1);
        float v = 0.f;
        if (l < nrows) {
            int row = b * NN + l0 + l;
            v = (ci < CC) ? g_sage[row * CC + ci] : feat[(size_t)row * CC + (ci - CC)];
        }
        shX[ci * PL2 + l] = v;
    }

    float acc0[8], acc1[8], acc2[8], acc3[8];
    #pragma unroll
    for (int l = 0; l < 8; l++) { acc0[l] = 0; acc1[l] = 0; acc2[l] = 0; acc3[l] = 0; }

    for (int cc0 = 0; cc0 < C2; cc0 += CI2) {
        __syncthreads();
        for (int idx = tid; idx < CI2 * 3 * C2; idx += 512) {
            int co = idx & (C2 - 1); int rem = idx >> 8;   // rem = ci*3+k
            shW[rem * C2 + co] = w2[co * (C2 * 3) + cc0 * 3 + rem];
        }
        __syncthreads();
        #pragma unroll 2
        for (int ci = 0; ci < CI2; ci++) {
            float x[10];
            int base = (cc0 + ci) * PL2 + 8 * ws;
            #pragma unroll
            for (int i = 0; i < 10; i++) x[i] = shX[base + i];
            #pragma unroll
            for (int k = 0; k < 3; k++) {
                float4 w = *(const float4*)&shW[(ci * 3 + k) * C2 + 4 * coq];
                #pragma unroll
                for (int l = 0; l < 8; l++) {
                    float xv = x[l + k];
                    acc0[l] = fmaf(w.x, xv, acc0[l]);
                    acc1[l] = fmaf(w.y, xv, acc1[l]);
                    acc2[l] = fmaf(w.z, xv, acc2[l]);
                    acc3[l] = fmaf(w.w, xv, acc3[l]);
                }
            }
        }
    }

    int co0 = 4 * coq;
    float bb[4] = {b2[co0], b2[co0 + 1], b2[co0 + 2], b2[co0 + 3]};
    float mmax[4], mmin[4], msum[4], mssq[4];
    #pragma unroll
    for (int j = 0; j < 4; j++) { mmax[j] = fNINF(); mmin[j] = fPINF(); msum[j] = 0; mssq[j] = 0; }
    int lbase = l0 + 8 * ws;
    #pragma unroll
    for (int l = 0; l < 8; l++) {
        if (lbase + l <= NN - 3) {
            float v[4] = {acc0[l] + bb[0], acc1[l] + bb[1], acc2[l] + bb[2], acc3[l] + bb[3]};
            #pragma unroll
            for (int j = 0; j < 4; j++) {
                mmax[j] = fmaxf(mmax[j], v[j]);
                mmin[j] = fminf(mmin[j], v[j]);
                msum[j] += v[j];
                mssq[j] += v[j] * v[j];
            }
        }
    }
    #pragma unroll
    for (int j = 0; j < 4; j++) {
        int co = co0 + j;
        atomicAdd(&g_sum2[co], msum[j]);
        atomicAdd(&g_ssq2[co], mssq[j]);
        atomicMaxF(&g_max2[b * C2 + co], mmax[j]);
        atomicMinF(&g_min2[b * C2 + co], mmin[j]);
    }
}

// ---------------- finish: BN affine + relu + pool + linears + product ----------------
__global__ __launch_bounds__(512) void k_final(const float* __restrict__ g1, const float* __restrict__ be1,
                                               const float* __restrict__ g2, const float* __restrict__ be2,
                                               const float* __restrict__ l1w, const float* __restrict__ l1b,
                                               const float* __restrict__ l2w, const float* __restrict__ l2b,
                                               float* __restrict__ out) {
    __shared__ float p1[BB * CC];
    __shared__ float p2[BB * C2];
    int tid = threadIdx.x;
    const float cnt = (float)(BB * (NN - 2));

    for (int c = tid; c < CC; c += 512) {
        float m = g_sum1[c] / cnt;
        float v = g_ssq1[c] / cnt - m * m;
        float a = g1[c] * rsqrtf(fmaxf(v, 0.f) + 1e-5f);
        float o = be1[c] - a * m;
        for (int b = 0; b < BB; b++) {
            float x = (a >= 0.f) ? g_max1[b * CC + c] : g_min1[b * CC + c];
            p1[b * CC + c] = fmaxf(a * x + o, 0.f);
        }
    }
    for (int c = tid; c < C2; c += 512) {
        float m = g_sum2[c] / cnt;
        float v = g_ssq2[c] / cnt - m * m;
        float a = g2[c] * rsqrtf(fmaxf(v, 0.f) + 1e-5f);
        float o = be2[c] - a * m;
        for (int b = 0; b < BB; b++) {
            float x = (a >= 0.f) ? g_max2[b * C2 + c] : g_min2[b * C2 + c];
            p2[b * C2 + c] = fmaxf(a * x + o, 0.f);
        }
    }
    __syncthreads();
    if (tid < 32) {
        int b = tid >> 1, j = tid & 1;
        float s1 = l1b[j];
        for (int c = 0; c < CC; c++) s1 += p1[b * CC + c] * l1w[j * CC + c];
        float s2 = l2b[j];
        for (int c = 0; c < C2; c++) s2 += p2[b * C2 + c] * l2w[j * C2 + c];
        out[tid] = s1 * s2;
    }
}

// ---------------- host ----------------
extern "C" void kernel_launch(void* const* d_in, const int* in_sizes, int n_in,
                              void* d_out, int out_size) {
    const float* feature = (const float*)d_in[0];
    const void*  topo    = d_in[1];
    const float* lin_l_w = (const float*)d_in[3];
    const float* lin_l_b = (const float*)d_in[4];
    const float* lin_r_w = (const float*)d_in[5];
    const float* conv1_w = (const float*)d_in[6];
    const float* conv1_b = (const float*)d_in[7];
    const float* bn1_g   = (const float*)d_in[8];
    const float* bn1_b   = (const float*)d_in[9];
    const float* conv2_w = (const float*)d_in[10];
    const float* conv2_b = (const float*)d_in[11];
    const float* bn2_g   = (const float*)d_in[12];
    const float* bn2_b   = (const float*)d_in[13];
    const float* lin1_w  = (const float*)d_in[14];
    const float* lin1_b  = (const float*)d_in[15];
    const float* lin2_w  = (const float*)d_in[16];
    const float* lin2_b  = (const float*)d_in[17];
    float* out = (float*)d_out;

    const int SM_SAGE  = (CC * PW * 2 + CC * PA * 2) * 4;          // 204800 B
    const int SM_CONV1 = (CC * PL1 + CI1 * 3 * CC) * 4;            // 165376 B
    const int SM_CONV2 = (C2 * PL2 + CI2 * 3 * C2) * 4;            // 166912 B
    cudaFuncSetAttribute(k_sage,  cudaFuncAttributeMaxDynamicSharedMemorySize, SM_SAGE);
    cudaFuncSetAttribute(k_conv1, cudaFuncAttributeMaxDynamicSharedMemorySize, SM_CONV1);
    cudaFuncSetAttribute(k_conv2, cudaFuncAttributeMaxDynamicSharedMemorySize, SM_CONV2);

    k_detect<<<1, 32>>>((const unsigned int*)topo);
    k_init<<<256, 256>>>();
    k_hist<<<EDGES / 256, 256>>>(topo);
    k_scan1<<<256, 256>>>();
    k_scan2<<<1, 256>>>();
    k_scan3<<<256, 256>>>();
    k_scatter<<<EDGES / 256, 256>>>(topo);
    k_agg<<<NUM_NODES / 8, 256>>>(feature);
    k_sage<<<NUM_NODES / RPB, 256, SM_SAGE>>>(feature, lin_l_w, lin_l_b, lin_r_w);
    k_conv1<<<dim3(NN / L1T, BB), 512, SM_CONV1>>>(conv1_w, conv1_b);
    k_conv2<<<dim3(NN / L2T, BB), 512, SM_CONV2>>>(feature, conv2_w, conv2_b);
    k_final<<<1, 512>>>(bn1_g, bn1_b, bn2_g, bn2_b,
                        lin1_w, lin1_b, lin2_w, lin2_b, out);
}

// round 3
// speedup vs baseline: 1.1002x; 1.0511x over previous
#include <cuda_runtime.h>
#include <math.h>

#define BB 16
#define NN 4096
#define CC 128
#define C2 256
#define NUM_NODES 65536
#define EDGES 2097152

// ---------------- device scratch (static, no allocs) ----------------
static __device__ int   g_is64;
static __device__ int   g_count[NUM_NODES];
static __device__ int   g_off[NUM_NODES + 1];
static __device__ int   g_cursor[NUM_NODES];
static __device__ int   g_blksum[256];
static __device__ int   g_src[EDGES];
static __device__ float g_agg[NUM_NODES * CC];
static __device__ float g_sage[NUM_NODES * CC];
static __device__ float g_sum1[CC],  g_ssq1[CC];
static __device__ float g_max1[BB * CC], g_min1[BB * CC];
static __device__ float g_sum2[C2],  g_ssq2[C2];
static __device__ float g_max2[BB * C2], g_min2[BB * C2];

__device__ __forceinline__ float fNINF() { return __int_as_float(0xff800000u); }
__device__ __forceinline__ float fPINF() { return __int_as_float(0x7f800000u); }

__device__ __forceinline__ void atomicMaxF(float* a, float v) {
    if (v >= 0.f) atomicMax((int*)a, __float_as_int(v));
    else          atomicMin((unsigned int*)a, __float_as_uint(v));
}
__device__ __forceinline__ void atomicMinF(float* a, float v) {
    if (v >= 0.f) atomicMin((int*)a, __float_as_int(v));
    else          atomicMax((unsigned int*)a, __float_as_uint(v));
}

// ---------------- packed f32x2 helpers (Blackwell FFMA2) ----------------
#define FMA2(acc, a, b) asm("fma.rn.f32x2 %0, %1, %2, %0;" : "+l"(acc) : "l"(a), "l"(b))

__device__ __forceinline__ unsigned long long packdup(float v) {
    unsigned long long r;
    unsigned u = __float_as_uint(v);
    asm("mov.b64 %0, {%1, %1};" : "=l"(r) : "r"(u));
    return r;
}
__device__ __forceinline__ float2 unpack2(unsigned long long p) {
    unsigned lo, hi;
    asm("mov.b64 {%0, %1}, %2;" : "=r"(lo), "=r"(hi) : "l"(p));
    return make_float2(__uint_as_float(lo), __uint_as_float(hi));
}

// ---------------- dtype sniff: int64 vs int32 topo ----------------
__global__ void k_detect(const unsigned int* __restrict__ topo_u32) {
    if (threadIdx.x == 0 && blockIdx.x == 0) {
        int is64 = 1;
        #pragma unroll 1
        for (int i = 0; i < 32; i++) {
            if (topo_u32[2 * i + 1] != 0u) { is64 = 0; break; }
        }
        g_is64 = is64;
    }
}

// ---------------- init scratch each run (graph-replay safe) ----------------
__global__ void k_init() {
    int i = blockIdx.x * blockDim.x + threadIdx.x;
    if (i < NUM_NODES) g_count[i] = 0;
    if (i < CC) { g_sum1[i] = 0.f; g_ssq1[i] = 0.f; }
    if (i < C2) { g_sum2[i] = 0.f; g_ssq2[i] = 0.f; }
    if (i < BB * CC) { g_max1[i] = fNINF(); g_min1[i] = fPINF(); }
    if (i < BB * C2) { g_max2[i] = fNINF(); g_min2[i] = fPINF(); }
}

// ---------------- CSR build ----------------
__global__ void k_hist(const void* __restrict__ topo) {
    int e = blockIdx.x * blockDim.x + threadIdx.x;
    if (e >= EDGES) return;
    int d = g_is64 ? (int)((const long long*)topo)[EDGES + e]
                   : ((const int*)topo)[EDGES + e];
    atomicAdd(&g_count[d], 1);
}

// 3-phase multi-block scan of g_count -> g_off/g_cursor
__global__ void k_scan1() {
    __shared__ int sh[256];
    int b = blockIdx.x, t = threadIdx.x;
    int i = b * 256 + t;
    int c = g_count[i];
    sh[t] = c;
    __syncthreads();
    for (int ofs = 1; ofs < 256; ofs <<= 1) {
        int v = (t >= ofs) ? sh[t - ofs] : 0;
        __syncthreads();
        sh[t] += v;
        __syncthreads();
    }
    g_off[i] = sh[t] - c;          // block-relative exclusive prefix
    if (t == 255) g_blksum[b] = sh[255];
}

__global__ void k_scan2() {
    __shared__ int sh[256];
    int t = threadIdx.x;
    int c = g_blksum[t];
    sh[t] = c;
    __syncthreads();
    for (int ofs = 1; ofs < 256; ofs <<= 1) {
        int v = (t >= ofs) ? sh[t - ofs] : 0;
        __syncthreads();
        sh[t] += v;
        __syncthreads();
    }
    g_blksum[t] = sh[t] - c;       // exclusive block offsets
}

__global__ void k_scan3() {
    int b = blockIdx.x, t = threadIdx.x;
    int i = b * 256 + t;
    int v = g_off[i] + g_blksum[b];
    g_off[i] = v;
    g_cursor[i] = v;
    if (i == NUM_NODES - 1) g_off[NUM_NODES] = EDGES;
}

__global__ void k_scatter(const void* __restrict__ topo) {
    int e = blockIdx.x * blockDim.x + threadIdx.x;
    if (e >= EDGES) return;
    int s, d;
    if (g_is64) {
        s = (int)((const long long*)topo)[e];
        d = (int)((const long long*)topo)[EDGES + e];
    } else {
        s = ((const int*)topo)[e];
        d = ((const int*)topo)[EDGES + e];
    }
    int pos = atomicAdd(&g_cursor[d], 1);
    g_src[pos] = s;
}

// ---------------- per-node max aggregation (warp per node, 4-edge MLP) ----------------
__global__ __launch_bounds__(256) void k_agg(const float* __restrict__ feat) {
    int gwarp = (blockIdx.x * blockDim.x + threadIdx.x) >> 5;
    int lane = threadIdx.x & 31;
    if (gwarp >= NUM_NODES) return;
    int beg = g_off[gwarp], end = g_off[gwarp + 1];
    float4 acc = make_float4(fNINF(), fNINF(), fNINF(), fNINF());
    int i = beg;
    for (; i + 4 <= end; i += 4) {
        int s0 = g_src[i], s1 = g_src[i + 1], s2 = g_src[i + 2], s3 = g_src[i + 3];
        float4 v0 = __ldg(((const float4*)(feat + (size_t)s0 * CC)) + lane);
        float4 v1 = __ldg(((const float4*)(feat + (size_t)s1 * CC)) + lane);
        float4 v2 = __ldg(((const float4*)(feat + (size_t)s2 * CC)) + lane);
        float4 v3 = __ldg(((const float4*)(feat + (size_t)s3 * CC)) + lane);
        float mx = fmaxf(fmaxf(v0.x, v1.x), fmaxf(v2.x, v3.x));
        float my = fmaxf(fmaxf(v0.y, v1.y), fmaxf(v2.y, v3.y));
        float mz = fmaxf(fmaxf(v0.z, v1.z), fmaxf(v2.z, v3.z));
        float mw = fmaxf(fmaxf(v0.w, v1.w), fmaxf(v2.w, v3.w));
        acc.x = fmaxf(acc.x, mx);
        acc.y = fmaxf(acc.y, my);
        acc.z = fmaxf(acc.z, mz);
        acc.w = fmaxf(acc.w, mw);
    }
    for (; i < end; i++) {
        int s0 = g_src[i];
        float4 v0 = __ldg(((const float4*)(feat + (size_t)s0 * CC)) + lane);
        acc.x = fmaxf(acc.x, v0.x);
        acc.y = fmaxf(acc.y, v0.y);
        acc.z = fmaxf(acc.z, v0.z);
        acc.w = fmaxf(acc.w, v0.w);
    }
    if (beg == end) acc = make_float4(0.f, 0.f, 0.f, 0.f);  // empty segment -> 0
    ((float4*)(g_agg + (size_t)gwarp * CC))[lane] = acc;
}

// ---------------- sage = agg@Wl^T + b + feat@Wr^T, then row L2-normalize ----------------
#define RPB 64
#define PW 132
#define PA 68
__global__ __launch_bounds__(256) void k_sage(const float* __restrict__ feat,
                                              const float* __restrict__ Wl,
                                              const float* __restrict__ bl,
                                              const float* __restrict__ Wr) {
    extern __shared__ float sm[];
    float* shWl = sm;                     // [k][n] padded PW
    float* shWr = shWl + CC * PW;
    float* shA  = shWr + CC * PW;         // [k][r] padded PA
    float* shF  = shA + CC * PA;

    int tid = threadIdx.x;
    int lane = tid & 31, ws = tid >> 5;
    int row0 = blockIdx.x * RPB;

    for (int idx = tid; idx < CC * CC; idx += 256) {
        int k = idx & (CC - 1), n = idx >> 7;
        shWl[k * PW + n] = Wl[idx];   // Wl is [n][k], idx=n*128+k (coalesced)
        shWr[k * PW + n] = Wr[idx];
    }
    for (int idx = tid; idx < RPB * CC; idx += 256) {
        int k = idx & (CC - 1), r = idx >> 7;
        shA[k * PA + r] = g_agg[(row0 + r) * CC + k];
        shF[k * PA + r] = feat[(size_t)(row0 + r) * CC + k];
    }
    __syncthreads();

    unsigned long long acc01[8], acc23[8];
    #pragma unroll
    for (int r = 0; r < 8; r++) { acc01[r] = 0ull; acc23[r] = 0ull; }

    #pragma unroll 2
    for (int k = 0; k < CC; k++) {
        ulonglong2 wl = *(const ulonglong2*)&shWl[k * PW + 4 * lane];
        ulonglong2 wr = *(const ulonglong2*)&shWr[k * PW + 4 * lane];
        float4 a0 = *(const float4*)&shA[k * PA + 8 * ws];
        float4 a1 = *(const float4*)&shA[k * PA + 8 * ws + 4];
        float4 f0 = *(const float4*)&shF[k * PA + 8 * ws];
        float4 f1 = *(const float4*)&shF[k * PA + 8 * ws + 4];
        float av[8] = {a0.x, a0.y, a0.z, a0.w, a1.x, a1.y, a1.z, a1.w};
        float fv[8] = {f0.x, f0.y, f0.z, f0.w, f1.x, f1.y, f1.z, f1.w};
        #pragma unroll
        for (int r = 0; r < 8; r++) {
            unsigned long long ap = packdup(av[r]);
            unsigned long long fp = packdup(fv[r]);
            FMA2(acc01[r], wl.x, ap);
            FMA2(acc23[r], wl.y, ap);
            FMA2(acc01[r], wr.x, fp);
            FMA2(acc23[r], wr.y, fp);
        }
    }

    float b0 = bl[4 * lane], b1 = bl[4 * lane + 1], b2 = bl[4 * lane + 2], b3 = bl[4 * lane + 3];
    #pragma unroll
    for (int r = 0; r < 8; r++) {
        float2 p01 = unpack2(acc01[r]);
        float2 p23 = unpack2(acc23[r]);
        float v0 = p01.x + b0, v1 = p01.y + b1, v2 = p23.x + b2, v3 = p23.y + b3;
        float ss = v0 * v0 + v1 * v1 + v2 * v2 + v3 * v3;
        #pragma unroll
        for (int o = 16; o > 0; o >>= 1) ss += __shfl_xor_sync(0xffffffffu, ss, o);
        float inv = 1.f / fmaxf(sqrtf(ss), 1e-12f);
        float4 o4 = make_float4(v0 * inv, v1 * inv, v2 * inv, v3 * inv);
        *(float4*)&g_sage[(row0 + 8 * ws + r) * CC + 4 * lane] = o4;
    }
}

// ---------------- fused conv1(k=3) + stats, 512 threads, FFMA2 ----------------
#define L1T 128
#define PL1 131
#define CI1 64
__global__ __launch_bounds__(512) void k_conv1(const float* __restrict__ w1,
                                               const float* __restrict__ b1) {
    extern __shared__ float sm[];
    float* shX = sm;                 // [ci][l] padded PL1, (L1T+2) rows
    float* shW = sm + CC * PL1;      // [(ci*3+k)][co]
    int tid = threadIdx.x;
    int coq = tid & 31, ws = tid >> 5;   // 32 co-quads, 16 l-slots x 8
    int b = blockIdx.y;
    int l0 = blockIdx.x * L1T;
    int nrows = NN - l0; if (nrows > L1T + 2) nrows = L1T + 2;

    for (int idx = tid; idx < (L1T + 2) * CC; idx += 512) {
        int l = idx >> 7, ci = idx & (CC - 1);
        shX[ci * PL1 + l] = (l < nrows) ? g_sage[(b * NN + l0 + l) * CC + ci] : 0.f;
    }

    unsigned long long acc01[8], acc23[8];
    #pragma unroll
    for (int l = 0; l < 8; l++) { acc01[l] = 0ull; acc23[l] = 0ull; }

    for (int cc0 = 0; cc0 < CC; cc0 += CI1) {
        __syncthreads();
        for (int idx = tid; idx < CI1 * 3 * CC; idx += 512) {
            int co = idx & (CC - 1); int rem = idx >> 7;  // rem = ci*3+k
            shW[rem * CC + co] = w1[co * (CC * 3) + cc0 * 3 + rem];
        }
        __syncthreads();
        #pragma unroll 2
        for (int ci = 0; ci < CI1; ci++) {
            int base = (cc0 + ci) * PL1 + 8 * ws;
            unsigned long long xp[10];
            #pragma unroll
            for (int i = 0; i < 10; i++) xp[i] = packdup(shX[base + i]);
            #pragma unroll
            for (int k = 0; k < 3; k++) {
                ulonglong2 w = *(const ulonglong2*)&shW[(ci * 3 + k) * CC + 4 * coq];
                #pragma unroll
                for (int l = 0; l < 8; l++) {
                    FMA2(acc01[l], w.x, xp[l + k]);
                    FMA2(acc23[l], w.y, xp[l + k]);
                }
            }
        }
    }

    int co0 = 4 * coq;
    float bb[4] = {b1[co0], b1[co0 + 1], b1[co0 + 2], b1[co0 + 3]};
    float mmax[4], mmin[4], msum[4], mssq[4];
    #pragma unroll
    for (int j = 0; j < 4; j++) { mmax[j] = fNINF(); mmin[j] = fPINF(); msum[j] = 0; mssq[j] = 0; }
    int lbase = l0 + 8 * ws;
    #pragma unroll
    for (int l = 0; l < 8; l++) {
        if (lbase + l <= NN - 3) {
            float2 p01 = unpack2(acc01[l]);
            float2 p23 = unpack2(acc23[l]);
            float v[4] = {p01.x + bb[0], p01.y + bb[1], p23.x + bb[2], p23.y + bb[3]};
            #pragma unroll
            for (int j = 0; j < 4; j++) {
                mmax[j] = fmaxf(mmax[j], v[j]);
                mmin[j] = fminf(mmin[j], v[j]);
                msum[j] += v[j];
                mssq[j] += v[j] * v[j];
            }
        }
    }
    #pragma unroll
    for (int j = 0; j < 4; j++) {
        int co = co0 + j;
        atomicAdd(&g_sum1[co], msum[j]);
        atomicAdd(&g_ssq1[co], mssq[j]);
        atomicMaxF(&g_max1[b * CC + co], mmax[j]);
        atomicMinF(&g_min1[b * CC + co], mmin[j]);
    }
}

// ---------------- fused conv2 (2C channels), 512 threads, FFMA2 ----------------
#define L2T 64
#define PL2 67
#define CI2 32
__global__ __launch_bounds__(512) void k_conv2(const float* __restrict__ feat,
                                               const float* __restrict__ w2,
                                               const float* __restrict__ b2) {
    extern __shared__ float sm[];
    float* shX = sm;                 // [ci][l] padded PL2, 66 rows, ci<256
    float* shW = sm + C2 * PL2;      // [(ci*3+k)][co]
    int tid = threadIdx.x;
    int coq = tid & 63, ws = tid >> 6;   // 64 co-quads, 8 l-slots x 8
    int b = blockIdx.y;
    int l0 = blockIdx.x * L2T;
    int nrows = NN - l0; if (nrows > L2T + 2) nrows = L2T + 2;

    for (int idx = tid; idx < (L2T + 2) * C2; idx += 512) {
        int l = idx >> 8, ci = idx & (C2 - 1);
        float v = 0.f;
        if (l < nrows) {
            int row = b * NN + l0 + l;
            v = (ci < CC) ? g_sage[row * CC + ci] : feat[(size_t)row * CC + (ci - CC)];
        }
        shX[ci * PL2 + l] = v;
    }

    unsigned long long acc01[8], acc23[8];
    #pragma unroll
    for (int l = 0; l < 8; l++) { acc01[l] = 0ull; acc23[l] = 0ull; }

    for (int cc0 = 0; cc0 < C2; cc0 += CI2) {
        __syncthreads();
        for (int idx = tid; idx < CI2 * 3 * C2; idx += 512) {
            int co = idx & (C2 - 1); int rem = idx >> 8;   // rem = ci*3+k
            shW[rem * C2 + co] = w2[co * (C2 * 3) + cc0 * 3 + rem];
        }
        __syncthreads();
        #pragma unroll 2
        for (int ci = 0; ci < CI2; ci++) {
            int base = (cc0 + ci) * PL2 + 8 * ws;
            unsigned long long xp[10];
            #pragma unroll
            for (int i = 0; i < 10; i++) xp[i] = packdup(shX[base + i]);
            #pragma unroll
            for (int k = 0; k < 3; k++) {
                ulonglong2 w = *(const ulonglong2*)&shW[(ci * 3 + k) * C2 + 4 * coq];
                #pragma unroll
                for (int l = 0; l < 8; l++) {
                    FMA2(acc01[l], w.x, xp[l + k]);
                    FMA2(acc23[l], w.y, xp[l + k]);
                }
            }
        }
    }

    int co0 = 4 * coq;
    float bb[4] = {b2[co0], b2[co0 + 1], b2[co0 + 2], b2[co0 + 3]};
    float mmax[4], mmin[4], msum[4], mssq[4];
    #pragma unroll
    for (int j = 0; j < 4; j++) { mmax[j] = fNINF(); mmin[j] = fPINF(); msum[j] = 0; mssq[j] = 0; }
    int lbase = l0 + 8 * ws;
    #pragma unroll
    for (int l = 0; l < 8; l++) {
        if (lbase + l <= NN - 3) {
            float2 p01 = unpack2(acc01[l]);
            float2 p23 = unpack2(acc23[l]);
            float v[4] = {p01.x + bb[0], p01.y + bb[1], p23.x + bb[2], p23.y + bb[3]};
            #pragma unroll
            for (int j = 0; j < 4; j++) {
                mmax[j] = fmaxf(mmax[j], v[j]);
                mmin[j] = fminf(mmin[j], v[j]);
                msum[j] += v[j];
                mssq[j] += v[j] * v[j];
            }
        }
    }
    #pragma unroll
    for (int j = 0; j < 4; j++) {
        int co = co0 + j;
        atomicAdd(&g_sum2[co], msum[j]);
        atomicAdd(&g_ssq2[co], mssq[j]);
        atomicMaxF(&g_max2[b * C2 + co], mmax[j]);
        atomicMinF(&g_min2[b * C2 + co], mmin[j]);
    }
}

// ---------------- finish: BN affine + relu + pool + linears + product ----------------
__global__ __launch_bounds__(512) void k_final(const float* __restrict__ g1, const float* __restrict__ be1,
                                               const float* __restrict__ g2, const float* __restrict__ be2,
                                               const float* __restrict__ l1w, const float* __restrict__ l1b,
                                               const float* __restrict__ l2w, const float* __restrict__ l2b,
                                               float* __restrict__ out) {
    __shared__ float p1[BB * CC];
    __shared__ float p2[BB * C2];
    int tid = threadIdx.x;
    const float cnt = (float)(BB * (NN - 2));

    for (int c = tid; c < CC; c += 512) {
        float m = g_sum1[c] / cnt;
        float v = g_ssq1[c] / cnt - m * m;
        float a = g1[c] * rsqrtf(fmaxf(v, 0.f) + 1e-5f);
        float o = be1[c] - a * m;
        for (int b = 0; b < BB; b++) {
            float x = (a >= 0.f) ? g_max1[b * CC + c] : g_min1[b * CC + c];
            p1[b * CC + c] = fmaxf(a * x + o, 0.f);
        }
    }
    for (int c = tid; c < C2; c += 512) {
        float m = g_sum2[c] / cnt;
        float v = g_ssq2[c] / cnt - m * m;
        float a = g2[c] * rsqrtf(fmaxf(v, 0.f) + 1e-5f);
        float o = be2[c] - a * m;
        for (int b = 0; b < BB; b++) {
            float x = (a >= 0.f) ? g_max2[b * C2 + c] : g_min2[b * C2 + c];
            p2[b * C2 + c] = fmaxf(a * x + o, 0.f);
        }
    }
    __syncthreads();
    if (tid < 32) {
        int b = tid >> 1, j = tid & 1;
        float s1 = l1b[j];
        for (int c = 0; c < CC; c++) s1 += p1[b * CC + c] * l1w[j * CC + c];
        float s2 = l2b[j];
        for (int c = 0; c < C2; c++) s2 += p2[b * C2 + c] * l2w[j * C2 + c];
        out[tid] = s1 * s2;
    }
}

// ---------------- host ----------------
extern "C" void kernel_launch(void* const* d_in, const int* in_sizes, int n_in,
                              void* d_out, int out_size) {
    const float* feature = (const float*)d_in[0];
    const void*  topo    = d_in[1];
    const float* lin_l_w = (const float*)d_in[3];
    const float* lin_l_b = (const float*)d_in[4];
    const float* lin_r_w = (const float*)d_in[5];
    const float* conv1_w = (const float*)d_in[6];
    const float* conv1_b = (const float*)d_in[7];
    const float* bn1_g   = (const float*)d_in[8];
    const float* bn1_b   = (const float*)d_in[9];
    const float* conv2_w = (const float*)d_in[10];
    const float* conv2_b = (const float*)d_in[11];
    const float* bn2_g   = (const float*)d_in[12];
    const float* bn2_b   = (const float*)d_in[13];
    const float* lin1_w  = (const float*)d_in[14];
    const float* lin1_b  = (const float*)d_in[15];
    const float* lin2_w  = (const float*)d_in[16];
    const float* lin2_b  = (const float*)d_in[17];
    float* out = (float*)d_out;

    const int SM_SAGE  = (CC * PW * 2 + CC * PA * 2) * 4;          // 204800 B
    const int SM_CONV1 = (CC * PL1 + CI1 * 3 * CC) * 4;            // 165376 B
    const int SM_CONV2 = (C2 * PL2 + CI2 * 3 * C2) * 4;            // 166912 B
    cudaFuncSetAttribute(k_sage,  cudaFuncAttributeMaxDynamicSharedMemorySize, SM_SAGE);
    cudaFuncSetAttribute(k_conv1, cudaFuncAttributeMaxDynamicSharedMemorySize, SM_CONV1);
    cudaFuncSetAttribute(k_conv2, cudaFuncAttributeMaxDynamicSharedMemorySize, SM_CONV2);

    k_detect<<<1, 32>>>((const unsigned int*)topo);
    k_init<<<256, 256>>>();
    k_hist<<<EDGES / 256, 256>>>(topo);
    k_scan1<<<256, 256>>>();
    k_scan2<<<1, 256>>>();
    k_scan3<<<256, 256>>>();
    k_scatter<<<EDGES / 256, 256>>>(topo);
    k_agg<<<NUM_NODES / 8, 256>>>(feature);
    k_sage<<<NUM_NODES / RPB, 256, SM_SAGE>>>(feature, lin_l_w, lin_l_b, lin_r_w);
    k_conv1<<<dim3(NN / L1T, BB), 512, SM_CONV1>>>(conv1_w, conv1_b);
    k_conv2<<<dim3(NN / L2T, BB), 512, SM_CONV2>>>(feature, conv2_w, conv2_b);
    k_final<<<1, 512>>>(bn1_g, bn1_b, bn2_g, bn2_b,
                        lin1_w, lin1_b, lin2_w, lin2_b, out);
}

// round 5
// speedup vs baseline: 1.1683x; 1.0619x over previous
#include <cuda_runtime.h>
#include <math.h>

#define BB 16
#define NN 4096
#define CC 128
#define C2 256
#define NUM_NODES 65536
#define EDGES 2097152

// ---------------- device scratch (static, no allocs) ----------------
static __device__ int   g_is64;
static __device__ int   g_count[NUM_NODES];
static __device__ int   g_off[NUM_NODES + 1];
static __device__ int   g_cursor[NUM_NODES];
static __device__ int   g_blksum[256];
static __device__ int   g_src[EDGES];
static __device__ float g_agg[NUM_NODES * CC];
static __device__ float g_sage[NUM_NODES * CC];
static __device__ float g_w1t[CC * 3 * CC];     // [ci*3+k][co]
static __device__ float g_w2t[C2 * 3 * C2];     // [ci*3+k][co]
static __device__ float g_sum1[CC],  g_ssq1[CC];
static __device__ float g_max1[BB * CC], g_min1[BB * CC];
static __device__ float g_sum2[C2],  g_ssq2[C2];
static __device__ float g_max2[BB * C2], g_min2[BB * C2];

__device__ __forceinline__ float fNINF() { return __int_as_float(0xff800000u); }
__device__ __forceinline__ float fPINF() { return __int_as_float(0x7f800000u); }

__device__ __forceinline__ void atomicMaxF(float* a, float v) {
    if (v >= 0.f) atomicMax((int*)a, __float_as_int(v));
    else          atomicMin((unsigned int*)a, __float_as_uint(v));
}
__device__ __forceinline__ void atomicMinF(float* a, float v) {
    if (v >= 0.f) atomicMin((int*)a, __float_as_int(v));
    else          atomicMax((unsigned int*)a, __float_as_uint(v));
}

// ---------------- packed f32x2 helpers (Blackwell FFMA2) ----------------
#define FMA2(acc, a, b) asm("fma.rn.f32x2 %0, %1, %2, %0;" : "+l"(acc) : "l"(a), "l"(b))

__device__ __forceinline__ unsigned long long packdup(float v) {
    unsigned long long r;
    unsigned u = __float_as_uint(v);
    asm("mov.b64 %0, {%1, %1};" : "=l"(r) : "r"(u));
    return r;
}
__device__ __forceinline__ float2 unpack2(unsigned long long p) {
    unsigned lo, hi;
    asm("mov.b64 {%0, %1}, %2;" : "=r"(lo), "=r"(hi) : "l"(p));
    return make_float2(__uint_as_float(lo), __uint_as_float(hi));
}

// ---------------- dtype sniff: int64 vs int32 topo ----------------
__global__ void k_detect(const unsigned int* __restrict__ topo_u32) {
    if (threadIdx.x == 0 && blockIdx.x == 0) {
        int is64 = 1;
        #pragma unroll 1
        for (int i = 0; i < 32; i++) {
            if (topo_u32[2 * i + 1] != 0u) { is64 = 0; break; }
        }
        g_is64 = is64;
    }
}

// ---------------- init scratch + weight transpose (graph-replay safe) ----------------
__global__ void k_init() {
    int i = blockIdx.x * blockDim.x + threadIdx.x;
    if (i < NUM_NODES) g_count[i] = 0;
    if (i < CC) { g_sum1[i] = 0.f; g_ssq1[i] = 0.f; }
    if (i < C2) { g_sum2[i] = 0.f; g_ssq2[i] = 0.f; }
    if (i < BB * CC) { g_max1[i] = fNINF(); g_min1[i] = fPINF(); }
    if (i < BB * C2) { g_max2[i] = fNINF(); g_min2[i] = fPINF(); }
}

__global__ void k_wprep(const float* __restrict__ w1, const float* __restrict__ w2) {
    int i = blockIdx.x * blockDim.x + threadIdx.x;
    if (i < CC * 3 * CC) {
        int r = i >> 7, co = i & (CC - 1);          // i = r*CC + co
        g_w1t[i] = w1[co * (CC * 3) + r];
    }
    if (i < C2 * 3 * C2) {
        int r = i >> 8, co = i & (C2 - 1);          // i = r*C2 + co
        g_w2t[i] = w2[co * (C2 * 3) + r];
    }
}

// ---------------- CSR build ----------------
__global__ void k_hist(const void* __restrict__ topo) {
    int e = blockIdx.x * blockDim.x + threadIdx.x;
    if (e >= EDGES) return;
    int d = g_is64 ? (int)((const long long*)topo)[EDGES + e]
                   : ((const int*)topo)[EDGES + e];
    atomicAdd(&g_count[d], 1);
}

__global__ void k_scan1() {
    __shared__ int sh[256];
    int b = blockIdx.x, t = threadIdx.x;
    int i = b * 256 + t;
    int c = g_count[i];
    sh[t] = c;
    __syncthreads();
    for (int ofs = 1; ofs < 256; ofs <<= 1) {
        int v = (t >= ofs) ? sh[t - ofs] : 0;
        __syncthreads();
        sh[t] += v;
        __syncthreads();
    }
    g_off[i] = sh[t] - c;
    if (t == 255) g_blksum[b] = sh[255];
}

__global__ void k_scan2() {
    __shared__ int sh[256];
    int t = threadIdx.x;
    int c = g_blksum[t];
    sh[t] = c;
    __syncthreads();
    for (int ofs = 1; ofs < 256; ofs <<= 1) {
        int v = (t >= ofs) ? sh[t - ofs] : 0;
        __syncthreads();
        sh[t] += v;
        __syncthreads();
    }
    g_blksum[t] = sh[t] - c;
}

__global__ void k_scan3() {
    int b = blockIdx.x, t = threadIdx.x;
    int i = b * 256 + t;
    int v = g_off[i] + g_blksum[b];
    g_off[i] = v;
    g_cursor[i] = v;
    if (i == NUM_NODES - 1) g_off[NUM_NODES] = EDGES;
}

__global__ void k_scatter(const void* __restrict__ topo) {
    int e = blockIdx.x * blockDim.x + threadIdx.x;
    if (e >= EDGES) return;
    int s, d;
    if (g_is64) {
        s = (int)((const long long*)topo)[e];
        d = (int)((const long long*)topo)[EDGES + e];
    } else {
        s = ((const int*)topo)[e];
        d = ((const int*)topo)[EDGES + e];
    }
    int pos = atomicAdd(&g_cursor[d], 1);
    g_src[pos] = s;
}

// ---------------- per-node max aggregation (warp per node, 4-edge MLP) ----------------
__global__ __launch_bounds__(256) void k_agg(const float* __restrict__ feat) {
    int gwarp = (blockIdx.x * blockDim.x + threadIdx.x) >> 5;
    int lane = threadIdx.x & 31;
    if (gwarp >= NUM_NODES) return;
    int beg = g_off[gwarp], end = g_off[gwarp + 1];
    float4 acc = make_float4(fNINF(), fNINF(), fNINF(), fNINF());
    int i = beg;
    for (; i + 4 <= end; i += 4) {
        int s0 = g_src[i], s1 = g_src[i + 1], s2 = g_src[i + 2], s3 = g_src[i + 3];
        float4 v0 = __ldg(((const float4*)(feat + (size_t)s0 * CC)) + lane);
        float4 v1 = __ldg(((const float4*)(feat + (size_t)s1 * CC)) + lane);
        float4 v2 = __ldg(((const float4*)(feat + (size_t)s2 * CC)) + lane);
        float4 v3 = __ldg(((const float4*)(feat + (size_t)s3 * CC)) + lane);
        float mx = fmaxf(fmaxf(v0.x, v1.x), fmaxf(v2.x, v3.x));
        float my = fmaxf(fmaxf(v0.y, v1.y), fmaxf(v2.y, v3.y));
        float mz = fmaxf(fmaxf(v0.z, v1.z), fmaxf(v2.z, v3.z));
        float mw = fmaxf(fmaxf(v0.w, v1.w), fmaxf(v2.w, v3.w));
        acc.x = fmaxf(acc.x, mx);
        acc.y = fmaxf(acc.y, my);
        acc.z = fmaxf(acc.z, mz);
        acc.w = fmaxf(acc.w, mw);
    }
    for (; i < end; i++) {
        int s0 = g_src[i];
        float4 v0 = __ldg(((const float4*)(feat + (size_t)s0 * CC)) + lane);
        acc.x = fmaxf(acc.x, v0.x);
        acc.y = fmaxf(acc.y, v0.y);
        acc.z = fmaxf(acc.z, v0.z);
        acc.w = fmaxf(acc.w, v0.w);
    }
    if (beg == end) acc = make_float4(0.f, 0.f, 0.f, 0.f);
    ((float4*)(g_agg + (size_t)gwarp * CC))[lane] = acc;
}

// ---------------- sage = agg@Wl^T + b + feat@Wr^T, then row L2-normalize ----------------
#define RPB 64
#define PW 132
#define PA 68
__global__ __launch_bounds__(256) void k_sage(const float* __restrict__ feat,
                                              const float* __restrict__ Wl,
                                              const float* __restrict__ bl,
                                              const float* __restrict__ Wr) {
    extern __shared__ float sm[];
    float* shWl = sm;
    float* shWr = shWl + CC * PW;
    float* shA  = shWr + CC * PW;
    float* shF  = shA + CC * PA;

    int tid = threadIdx.x;
    int lane = tid & 31, ws = tid >> 5;
    int row0 = blockIdx.x * RPB;

    for (int idx = tid; idx < CC * CC; idx += 256) {
        int k = idx & (CC - 1), n = idx >> 7;
        shWl[k * PW + n] = Wl[idx];
        shWr[k * PW + n] = Wr[idx];
    }
    for (int idx = tid; idx < RPB * CC; idx += 256) {
        int k = idx & (CC - 1), r = idx >> 7;
        shA[k * PA + r] = g_agg[(row0 + r) * CC + k];
        shF[k * PA + r] = feat[(size_t)(row0 + r) * CC + k];
    }
    __syncthreads();

    unsigned long long acc01[8], acc23[8];
    #pragma unroll
    for (int r = 0; r < 8; r++) { acc01[r] = 0ull; acc23[r] = 0ull; }

    #pragma unroll 2
    for (int k = 0; k < CC; k++) {
        ulonglong2 wl = *(const ulonglong2*)&shWl[k * PW + 4 * lane];
        ulonglong2 wr = *(const ulonglong2*)&shWr[k * PW + 4 * lane];
        float4 a0 = *(const float4*)&shA[k * PA + 8 * ws];
        float4 a1 = *(const float4*)&shA[k * PA + 8 * ws + 4];
        float4 f0 = *(const float4*)&shF[k * PA + 8 * ws];
        float4 f1 = *(const float4*)&shF[k * PA + 8 * ws + 4];
        float av[8] = {a0.x, a0.y, a0.z, a0.w, a1.x, a1.y, a1.z, a1.w};
        float fv[8] = {f0.x, f0.y, f0.z, f0.w, f1.x, f1.y, f1.z, f1.w};
        #pragma unroll
        for (int r = 0; r < 8; r++) {
            unsigned long long ap = packdup(av[r]);
            unsigned long long fp = packdup(fv[r]);
            FMA2(acc01[r], wl.x, ap);
            FMA2(acc23[r], wl.y, ap);
            FMA2(acc01[r], wr.x, fp);
            FMA2(acc23[r], wr.y, fp);
        }
    }

    float b0 = bl[4 * lane], b1 = bl[4 * lane + 1], b2 = bl[4 * lane + 2], b3 = bl[4 * lane + 3];
    #pragma unroll
    for (int r = 0; r < 8; r++) {
        float2 p01 = unpack2(acc01[r]);
        float2 p23 = unpack2(acc23[r]);
        float v0 = p01.x + b0, v1 = p01.y + b1, v2 = p23.x + b2, v3 = p23.y + b3;
        float ss = v0 * v0 + v1 * v1 + v2 * v2 + v3 * v3;
        #pragma unroll
        for (int o = 16; o > 0; o >>= 1) ss += __shfl_xor_sync(0xffffffffu, ss, o);
        float inv = 1.f / fmaxf(sqrtf(ss), 1e-12f);
        float4 o4 = make_float4(v0 * inv, v1 * inv, v2 * inv, v3 * inv);
        *(float4*)&g_sage[(row0 + 8 * ws + r) * CC + 4 * lane] = o4;
    }
}

// ---------------- fused conv1(k=3) + stats: 256 thr, 8co x 8l per thread ----------------
#define L1T 128
#define PL1 131
#define CI1 64
__global__ __launch_bounds__(256) void k_conv1(const float* __restrict__ b1) {
    extern __shared__ float sm[];
    float* shX = sm;                 // [ci][l] padded PL1, 130 rows used
    float* shW = sm + CC * PL1;      // [(ci*3+k)][co]
    int tid = threadIdx.x;
    int coq = tid & 15;              // 16 quads x 8 co = 128 co
    int lgrp = tid >> 4;             // 16 groups x 8 l = 128 l
    int b = blockIdx.y;
    int l0 = blockIdx.x * L1T;
    int nrows = NN - l0; if (nrows > L1T + 2) nrows = L1T + 2;

    for (int idx = tid; idx < (L1T + 2) * CC; idx += 256) {
        int l = idx >> 7, ci = idx & (CC - 1);
        shX[ci * PL1 + l] = (l < nrows) ? g_sage[(b * NN + l0 + l) * CC + ci] : 0.f;
    }

    unsigned long long acc[4][8];
    #pragma unroll
    for (int j = 0; j < 4; j++)
        #pragma unroll
        for (int l = 0; l < 8; l++) acc[j][l] = 0ull;

    for (int cc0 = 0; cc0 < CC; cc0 += CI1) {
        __syncthreads();
        for (int idx = tid; idx < CI1 * 3 * CC; idx += 256) {
            shW[idx] = g_w1t[cc0 * 3 * CC + idx];
        }
        __syncthreads();
        #pragma unroll 2
        for (int ci = 0; ci < CI1; ci++) {
            int base = (cc0 + ci) * PL1 + 8 * lgrp;
            unsigned long long xp[10];
            #pragma unroll
            for (int i = 0; i < 10; i++) xp[i] = packdup(shX[base + i]);
            #pragma unroll
            for (int k = 0; k < 3; k++) {
                const ulonglong2* wp = (const ulonglong2*)&shW[(ci * 3 + k) * CC + 8 * coq];
                ulonglong2 w0 = wp[0];
                ulonglong2 w1 = wp[1];
                #pragma unroll
                for (int l = 0; l < 8; l++) {
                    FMA2(acc[0][l], w0.x, xp[l + k]);
                    FMA2(acc[1][l], w0.y, xp[l + k]);
                    FMA2(acc[2][l], w1.x, xp[l + k]);
                    FMA2(acc[3][l], w1.y, xp[l + k]);
                }
            }
        }
    }

    int co0 = 8 * coq;
    float bb[8];
    #pragma unroll
    for (int j = 0; j < 8; j++) bb[j] = b1[co0 + j];
    float mmax[8], mmin[8], msum[8], mssq[8];
    #pragma unroll
    for (int j = 0; j < 8; j++) { mmax[j] = fNINF(); mmin[j] = fPINF(); msum[j] = 0; mssq[j] = 0; }
    int lbase = l0 + 8 * lgrp;
    #pragma unroll
    for (int l = 0; l < 8; l++) {
        if (lbase + l <= NN - 3) {
            float v[8];
            #pragma unroll
            for (int j = 0; j < 4; j++) {
                float2 p = unpack2(acc[j][l]);
                v[2 * j] = p.x + bb[2 * j];
                v[2 * j + 1] = p.y + bb[2 * j + 1];
            }
            #pragma unroll
            for (int j = 0; j < 8; j++) {
                mmax[j] = fmaxf(mmax[j], v[j]);
                mmin[j] = fminf(mmin[j], v[j]);
                msum[j] += v[j];
                mssq[j] += v[j] * v[j];
            }
        }
    }
    #pragma unroll
    for (int j = 0; j < 8; j++) {
        int co = co0 + j;
        atomicAdd(&g_sum1[co], msum[j]);
        atomicAdd(&g_ssq1[co], mssq[j]);
        atomicMaxF(&g_max1[b * CC + co], mmax[j]);
        atomicMinF(&g_min1[b * CC + co], mmin[j]);
    }
}

// ---------------- fused conv2 (2C ch): 256 thr, 8co x 8l per thread ----------------
#define L2T 64
#define PL2 67
#define CI2 32
__global__ __launch_bounds__(256) void k_conv2(const float* __restrict__ feat,
                                               const float* __restrict__ b2) {
    extern __shared__ float sm[];
    float* shX = sm;                 // [ci][l] padded PL2, 66 rows, ci<256
    float* shW = sm + C2 * PL2;      // [(ci*3+k)][co]
    int tid = threadIdx.x;
    int coq = tid & 31;              // 32 quads x 8 co = 256 co
    int ws = tid >> 5;               // 8 groups x 8 l = 64 l
    int b = blockIdx.y;
    int l0 = blockIdx.x * L2T;
    int nrows = NN - l0; if (nrows > L2T + 2) nrows = L2T + 2;

    for (int idx = tid; idx < (L2T + 2) * C2; idx += 256) {
        int l = idx >> 8, ci = idx & (C2 - 1);
        float v = 0.f;
        if (l < nrows) {
            int row = b * NN + l0 + l;
            v = (ci < CC) ? g_sage[row * CC + ci] : feat[(size_t)row * CC + (ci - CC)];
        }
        shX[ci * PL2 + l] = v;
    }

    unsigned long long acc[4][8];
    #pragma unroll
    for (int j = 0; j < 4; j++)
        #pragma unroll
        for (int l = 0; l < 8; l++) acc[j][l] = 0ull;

    for (int cc0 = 0; cc0 < C2; cc0 += CI2) {
        __syncthreads();
        for (int idx = tid; idx < CI2 * 3 * C2; idx += 256) {
            shW[idx] = g_w2t[cc0 * 3 * C2 + idx];
        }
        __syncthreads();
        #pragma unroll 2
        for (int ci = 0; ci < CI2; ci++) {
            int base = (cc0 + ci) * PL2 + 8 * ws;
            unsigned long long xp[10];
            #pragma unroll
            for (int i = 0; i < 10; i++) xp[i] = packdup(shX[base + i]);
            #pragma unroll
            for (int k = 0; k < 3; k++) {
                const ulonglong2* wp = (const ulonglong2*)&shW[(ci * 3 + k) * C2 + 8 * coq];
                ulonglong2 w0 = wp[0];
                ulonglong2 w1 = wp[1];
                #pragma unroll
                for (int l = 0; l < 8; l++) {
                    FMA2(acc[0][l], w0.x, xp[l + k]);
                    FMA2(acc[1][l], w0.y, xp[l + k]);
                    FMA2(acc[2][l], w1.x, xp[l + k]);
                    FMA2(acc[3][l], w1.y, xp[l + k]);
                }
            }
        }
    }

    int co0 = 8 * coq;
    float bb[8];
    #pragma unroll
    for (int j = 0; j < 8; j++) bb[j] = b2[co0 + j];
    float mmax[8], mmin[8], msum[8], mssq[8];
    #pragma unroll
    for (int j = 0; j < 8; j++) { mmax[j] = fNINF(); mmin[j] = fPINF(); msum[j] = 0; mssq[j] = 0; }
    int lbase = l0 + 8 * ws;
    #pragma unroll
    for (int l = 0; l < 8; l++) {
        if (lbase + l <= NN - 3) {
            float v[8];
            #pragma unroll
            for (int j = 0; j < 4; j++) {
                float2 p = unpack2(acc[j][l]);
                v[2 * j] = p.x + bb[2 * j];
                v[2 * j + 1] = p.y + bb[2 * j + 1];
            }
            #pragma unroll
            for (int j = 0; j < 8; j++) {
                mmax[j] = fmaxf(mmax[j], v[j]);
                mmin[j] = fminf(mmin[j], v[j]);
                msum[j] += v[j];
                mssq[j] += v[j] * v[j];
            }
        }
    }
    #pragma unroll
    for (int j = 0; j < 8; j++) {
        int co = co0 + j;
        atomicAdd(&g_sum2[co], msum[j]);
        atomicAdd(&g_ssq2[co], mssq[j]);
        atomicMaxF(&g_max2[b * C2 + co], mmax[j]);
        atomicMinF(&g_min2[b * C2 + co], mmin[j]);
    }
}

// ---------------- finish: BN affine + relu + pool + linears + product ----------------
__global__ __launch_bounds__(512) void k_final(const float* __restrict__ g1, const float* __restrict__ be1,
                                               const float* __restrict__ g2, const float* __restrict__ be2,
                                               const float* __restrict__ l1w, const float* __restrict__ l1b,
                                               const float* __restrict__ l2w, const float* __restrict__ l2b,
                                               float* __restrict__ out) {
    __shared__ float p1[BB * CC];
    __shared__ float p2[BB * C2];
    int tid = threadIdx.x;
    const float cnt = (float)(BB * (NN - 2));

    for (int c = tid; c < CC; c += 512) {
        float m = g_sum1[c] / cnt;
        float v = g_ssq1[c] / cnt - m * m;
        float a = g1[c] * rsqrtf(fmaxf(v, 0.f) + 1e-5f);
        float o = be1[c] - a * m;
        for (int b = 0; b < BB; b++) {
            float x = (a >= 0.f) ? g_max1[b * CC + c] : g_min1[b * CC + c];
            p1[b * CC + c] = fmaxf(a * x + o, 0.f);
        }
    }
    for (int c = tid; c < C2; c += 512) {
        float m = g_sum2[c] / cnt;
        float v = g_ssq2[c] / cnt - m * m;
        float a = g2[c] * rsqrtf(fmaxf(v, 0.f) + 1e-5f);
        float o = be2[c] - a * m;
        for (int b = 0; b < BB; b++) {
            float x = (a >= 0.f) ? g_max2[b * C2 + c] : g_min2[b * C2 + c];
            p2[b * C2 + c] = fmaxf(a * x + o, 0.f);
        }
    }
    __syncthreads();
    if (tid < 32) {
        int b = tid >> 1, j = tid & 1;
        float s1 = l1b[j];
        for (int c = 0; c < CC; c++) s1 += p1[b * CC + c] * l1w[j * CC + c];
        float s2 = l2b[j];
        for (int c = 0; c < C2; c++) s2 += p2[b * C2 + c] * l2w[j * C2 + c];
        out[tid] = s1 * s2;
    }
}

// ---------------- host ----------------
extern "C" void kernel_launch(void* const* d_in, const int* in_sizes, int n_in,
                              void* d_out, int out_size) {
    const float* feature = (const float*)d_in[0];
    const void*  topo    = d_in[1];
    const float* lin_l_w = (const float*)d_in[3];
    const float* lin_l_b = (const float*)d_in[4];
    const float* lin_r_w = (const float*)d_in[5];
    const float* conv1_w = (const float*)d_in[6];
    const float* conv1_b = (const float*)d_in[7];
    const float* bn1_g   = (const float*)d_in[8];
    const float* bn1_b   = (const float*)d_in[9];
    const float* conv2_w = (const float*)d_in[10];
    const float* conv2_b = (const float*)d_in[11];
    const float* bn2_g   = (const float*)d_in[12];
    const float* bn2_b   = (const float*)d_in[13];
    const float* lin1_w  = (const float*)d_in[14];
    const float* lin1_b  = (const float*)d_in[15];
    const float* lin2_w  = (const float*)d_in[16];
    const float* lin2_b  = (const float*)d_in[17];
    float* out = (float*)d_out;

    const int SM_SAGE  = (CC * PW * 2 + CC * PA * 2) * 4;          // 204800 B
    const int SM_CONV1 = (CC * PL1 + CI1 * 3 * CC) * 4;            // 165376 B
    const int SM_CONV2 = (C2 * PL2 + CI2 * 3 * C2) * 4;            // 166912 B
    cudaFuncSetAttribute(k_sage,  cudaFuncAttributeMaxDynamicSharedMemorySize, SM_SAGE);
    cudaFuncSetAttribute(k_conv1, cudaFuncAttributeMaxDynamicSharedMemorySize, SM_CONV1);
    cudaFuncSetAttribute(k_conv2, cudaFuncAttributeMaxDynamicSharedMemorySize, SM_CONV2);

    k_detect<<<1, 32>>>((const unsigned int*)topo);
    k_init<<<256, 256>>>();
    k_wprep<<<(C2 * 3 * C2 + 255) / 256, 256>>>(conv1_w, conv2_w);
    k_hist<<<EDGES / 256, 256>>>(topo);
    k_scan1<<<256, 256>>>();
    k_scan2<<<1, 256>>>();
    k_scan3<<<256, 256>>>();
    k_scatter<<<EDGES / 256, 256>>>(topo);
    k_agg<<<NUM_NODES / 8, 256>>>(feature);
    k_sage<<<NUM_NODES / RPB, 256, SM_SAGE>>>(feature, lin_l_w, lin_l_b, lin_r_w);
    k_conv1<<<dim3(NN / L1T, BB), 256, SM_CONV1>>>(conv1_b);
    k_conv2<<<dim3(NN / L2T, BB), 256, SM_CONV2>>>(feature, conv2_b);
    k_final<<<1, 512>>>(bn1_g, bn1_b, bn2_g, bn2_b,
                        lin1_w, lin1_b, lin2_w, lin2_b, out);
}

// round 7
// speedup vs baseline: 1.8393x; 1.5744x over previous
#include <cuda_runtime.h>
#include <cuda_bf16.h>
#include <mma.h>
#include <math.h>

using namespace nvcuda;

#define BB 16
#define NN 4096
#define CC 128
#define C2 256
#define NUM_NODES 65536
#define EDGES 2097152

// ---------------- device scratch (static, no allocs) ----------------
static __device__ int   g_is64;
static __device__ int   g_count[NUM_NODES];
static __device__ int   g_off[NUM_NODES + 1];
static __device__ int   g_cursor[NUM_NODES];
static __device__ int   g_blksum[256];
static __device__ int   g_src[EDGES];
static __device__ float g_agg[NUM_NODES * CC];
static __device__ float g_sage[NUM_NODES * CC];
static __device__ float g_w1t[CC * 3 * CC];          // conv1 weights [ci*3+k][co]
static __device__ uint4 g_w2h4[C2 * 1024 / 8];       // conv2 bf16 hi, [co][k'=1024] row-major
static __device__ uint4 g_w2l4[C2 * 1024 / 8];       // conv2 bf16 lo
static __device__ float g_sum1[CC],  g_ssq1[CC];
static __device__ float g_max1[BB * CC], g_min1[BB * CC];
static __device__ float g_sum2[C2],  g_ssq2[C2];
static __device__ float g_max2[BB * C2], g_min2[BB * C2];

__device__ __forceinline__ float fNINF() { return __int_as_float(0xff800000u); }
__device__ __forceinline__ float fPINF() { return __int_as_float(0x7f800000u); }

__device__ __forceinline__ void atomicMaxF(float* a, float v) {
    if (v >= 0.f) atomicMax((int*)a, __float_as_int(v));
    else          atomicMin((unsigned int*)a, __float_as_uint(v));
}
__device__ __forceinline__ void atomicMinF(float* a, float v) {
    if (v >= 0.f) atomicMin((int*)a, __float_as_int(v));
    else          atomicMax((unsigned int*)a, __float_as_uint(v));
}

// ---------------- packed f32x2 helpers (Blackwell FFMA2) ----------------
#define FMA2(acc, a, b) asm("fma.rn.f32x2 %0, %1, %2, %0;" : "+l"(acc) : "l"(a), "l"(b))

__device__ __forceinline__ unsigned long long packdup(float v) {
    unsigned long long r;
    unsigned u = __float_as_uint(v);
    asm("mov.b64 %0, {%1, %1};" : "=l"(r) : "r"(u));
    return r;
}
__device__ __forceinline__ float2 unpack2(unsigned long long p) {
    unsigned lo, hi;
    asm("mov.b64 {%0, %1}, %2;" : "=r"(lo), "=r"(hi) : "l"(p));
    return make_float2(__uint_as_float(lo), __uint_as_float(hi));
}

// ---------------- dtype sniff: int64 vs int32 topo ----------------
__global__ void k_detect(const unsigned int* __restrict__ topo_u32) {
    if (threadIdx.x == 0 && blockIdx.x == 0) {
        int is64 = 1;
        #pragma unroll 1
        for (int i = 0; i < 32; i++) {
            if (topo_u32[2 * i + 1] != 0u) { is64 = 0; break; }
        }
        g_is64 = is64;
    }
}

// ---------------- init scratch (graph-replay safe) ----------------
__global__ void k_init() {
    int i = blockIdx.x * blockDim.x + threadIdx.x;
    if (i < NUM_NODES) g_count[i] = 0;
    if (i < CC) { g_sum1[i] = 0.f; g_ssq1[i] = 0.f; }
    if (i < C2) { g_sum2[i] = 0.f; g_ssq2[i] = 0.f; }
    if (i < BB * CC) { g_max1[i] = fNINF(); g_min1[i] = fPINF(); }
    if (i < BB * C2) { g_max2[i] = fNINF(); g_min2[i] = fPINF(); }
}

// conv1 weight transpose [co][ci*3+k] -> [ci*3+k][co]
__global__ void k_wprep(const float* __restrict__ w1) {
    int i = blockIdx.x * blockDim.x + threadIdx.x;
    if (i < CC * 3 * CC) {
        int r = i >> 7, co = i & (CC - 1);
        g_w1t[i] = w1[co * (CC * 3) + r];
    }
}

// conv2 weights -> bf16 hi/lo, row-major [co][k'=ci*4+k] (k=3 zero)
__global__ void k_wprep2(const float* __restrict__ w2) {
    int i = blockIdx.x * blockDim.x + threadIdx.x;
    if (i >= C2 * 1024) return;
    int co = i >> 10, kp = i & 1023;
    int ci = kp >> 2, k = kp & 3;
    float v = (k < 3) ? w2[co * (C2 * 3) + ci * 3 + k] : 0.f;
    __nv_bfloat16 hi = __float2bfloat16(v);
    __nv_bfloat16 lo = __float2bfloat16(v - __bfloat162float(hi));
    ((__nv_bfloat16*)g_w2h4)[i] = hi;
    ((__nv_bfloat16*)g_w2l4)[i] = lo;
}

// ---------------- CSR build ----------------
__global__ void k_hist(const void* __restrict__ topo) {
    int e = blockIdx.x * blockDim.x + threadIdx.x;
    if (e >= EDGES) return;
    int d = g_is64 ? (int)((const long long*)topo)[EDGES + e]
                   : ((const int*)topo)[EDGES + e];
    atomicAdd(&g_count[d], 1);
}

__global__ void k_scan1() {
    __shared__ int sh[256];
    int b = blockIdx.x, t = threadIdx.x;
    int i = b * 256 + t;
    int c = g_count[i];
    sh[t] = c;
    __syncthreads();
    for (int ofs = 1; ofs < 256; ofs <<= 1) {
        int v = (t >= ofs) ? sh[t - ofs] : 0;
        __syncthreads();
        sh[t] += v;
        __syncthreads();
    }
    g_off[i] = sh[t] - c;
    if (t == 255) g_blksum[b] = sh[255];
}

__global__ void k_scan2() {
    __shared__ int sh[256];
    int t = threadIdx.x;
    int c = g_blksum[t];
    sh[t] = c;
    __syncthreads();
    for (int ofs = 1; ofs < 256; ofs <<= 1) {
        int v = (t >= ofs) ? sh[t - ofs] : 0;
        __syncthreads();
        sh[t] += v;
        __syncthreads();
    }
    g_blksum[t] = sh[t] - c;
}

__global__ void k_scan3() {
    int b = blockIdx.x, t = threadIdx.x;
    int i = b * 256 + t;
    int v = g_off[i] + g_blksum[b];
    g_off[i] = v;
    g_cursor[i] = v;
    if (i == NUM_NODES - 1) g_off[NUM_NODES] = EDGES;
}

__global__ void k_scatter(const void* __restrict__ topo) {
    int e = blockIdx.x * blockDim.x + threadIdx.x;
    if (e >= EDGES) return;
    int s, d;
    if (g_is64) {
        s = (int)((const long long*)topo)[e];
        d = (int)((const long long*)topo)[EDGES + e];
    } else {
        s = ((const int*)topo)[e];
        d = ((const int*)topo)[EDGES + e];
    }
    int pos = atomicAdd(&g_cursor[d], 1);
    g_src[pos] = s;
}

// ---------------- per-node max aggregation (warp per node, 4-edge MLP) ----------------
__global__ __launch_bounds__(256) void k_agg(const float* __restrict__ feat) {
    int gwarp = (blockIdx.x * blockDim.x + threadIdx.x) >> 5;
    int lane = threadIdx.x & 31;
    if (gwarp >= NUM_NODES) return;
    int beg = g_off[gwarp], end = g_off[gwarp + 1];
    float4 acc = make_float4(fNINF(), fNINF(), fNINF(), fNINF());
    int i = beg;
    for (; i + 4 <= end; i += 4) {
        int s0 = g_src[i], s1 = g_src[i + 1], s2 = g_src[i + 2], s3 = g_src[i + 3];
        float4 v0 = __ldg(((const float4*)(feat + (size_t)s0 * CC)) + lane);
        float4 v1 = __ldg(((const float4*)(feat + (size_t)s1 * CC)) + lane);
        float4 v2 = __ldg(((const float4*)(feat + (size_t)s2 * CC)) + lane);
        float4 v3 = __ldg(((const float4*)(feat + (size_t)s3 * CC)) + lane);
        float mx = fmaxf(fmaxf(v0.x, v1.x), fmaxf(v2.x, v3.x));
        float my = fmaxf(fmaxf(v0.y, v1.y), fmaxf(v2.y, v3.y));
        float mz = fmaxf(fmaxf(v0.z, v1.z), fmaxf(v2.z, v3.z));
        float mw = fmaxf(fmaxf(v0.w, v1.w), fmaxf(v2.w, v3.w));
        acc.x = fmaxf(acc.x, mx);
        acc.y = fmaxf(acc.y, my);
        acc.z = fmaxf(acc.z, mz);
        acc.w = fmaxf(acc.w, mw);
    }
    for (; i < end; i++) {
        int s0 = g_src[i];
        float4 v0 = __ldg(((const float4*)(feat + (size_t)s0 * CC)) + lane);
        acc.x = fmaxf(acc.x, v0.x);
        acc.y = fmaxf(acc.y, v0.y);
        acc.z = fmaxf(acc.z, v0.z);
        acc.w = fmaxf(acc.w, v0.w);
    }
    if (beg == end) acc = make_float4(0.f, 0.f, 0.f, 0.f);
    ((float4*)(g_agg + (size_t)gwarp * CC))[lane] = acc;
}

// ---------------- sage = agg@Wl^T + b + feat@Wr^T, then row L2-normalize ----------------
#define RPB 64
#define PW 132
#define PA 68
__global__ __launch_bounds__(256) void k_sage(const float* __restrict__ feat,
                                              const float* __restrict__ Wl,
                                              const float* __restrict__ bl,
                                              const float* __restrict__ Wr) {
    extern __shared__ float sm[];
    float* shWl = sm;
    float* shWr = shWl + CC * PW;
    float* shA  = shWr + CC * PW;
    float* shF  = shA + CC * PA;

    int tid = threadIdx.x;
    int lane = tid & 31, ws = tid >> 5;
    int row0 = blockIdx.x * RPB;

    for (int idx = tid; idx < CC * CC; idx += 256) {
        int k = idx & (CC - 1), n = idx >> 7;
        shWl[k * PW + n] = Wl[idx];
        shWr[k * PW + n] = Wr[idx];
    }
    for (int idx = tid; idx < RPB * CC; idx += 256) {
        int k = idx & (CC - 1), r = idx >> 7;
        shA[k * PA + r] = g_agg[(row0 + r) * CC + k];
        shF[k * PA + r] = feat[(size_t)(row0 + r) * CC + k];
    }
    __syncthreads();

    unsigned long long acc01[8], acc23[8];
    #pragma unroll
    for (int r = 0; r < 8; r++) { acc01[r] = 0ull; acc23[r] = 0ull; }

    #pragma unroll 2
    for (int k = 0; k < CC; k++) {
        ulonglong2 wl = *(const ulonglong2*)&shWl[k * PW + 4 * lane];
        ulonglong2 wr = *(const ulonglong2*)&shWr[k * PW + 4 * lane];
        float4 a0 = *(const float4*)&shA[k * PA + 8 * ws];
        float4 a1 = *(const float4*)&shA[k * PA + 8 * ws + 4];
        float4 f0 = *(const float4*)&shF[k * PA + 8 * ws];
        float4 f1 = *(const float4*)&shF[k * PA + 8 * ws + 4];
        float av[8] = {a0.x, a0.y, a0.z, a0.w, a1.x, a1.y, a1.z, a1.w};
        float fv[8] = {f0.x, f0.y, f0.z, f0.w, f1.x, f1.y, f1.z, f1.w};
        #pragma unroll
        for (int r = 0; r < 8; r++) {
            unsigned long long ap = packdup(av[r]);
            unsigned long long fp = packdup(fv[r]);
            FMA2(acc01[r], wl.x, ap);
            FMA2(acc23[r], wl.y, ap);
            FMA2(acc01[r], wr.x, fp);
            FMA2(acc23[r], wr.y, fp);
        }
    }

    float b0 = bl[4 * lane], b1 = bl[4 * lane + 1], b2 = bl[4 * lane + 2], b3 = bl[4 * lane + 3];
    #pragma unroll
    for (int r = 0; r < 8; r++) {
        float2 p01 = unpack2(acc01[r]);
        float2 p23 = unpack2(acc23[r]);
        float v0 = p01.x + b0, v1 = p01.y + b1, v2 = p23.x + b2, v3 = p23.y + b3;
        float ss = v0 * v0 + v1 * v1 + v2 * v2 + v3 * v3;
        #pragma unroll
        for (int o = 16; o > 0; o >>= 1) ss += __shfl_xor_sync(0xffffffffu, ss, o);
        float inv = 1.f / fmaxf(sqrtf(ss), 1e-12f);
        float4 o4 = make_float4(v0 * inv, v1 * inv, v2 * inv, v3 * inv);
        *(float4*)&g_sage[(row0 + 8 * ws + r) * CC + 4 * lane] = o4;
    }
}

// ---------------- fused conv1(k=3) + stats: FFMA2, 8co x 8l ----------------
#define L1T 128
#define PL1 131
#define CI1 64
__global__ __launch_bounds__(256) void k_conv1(const float* __restrict__ b1) {
    extern __shared__ float sm[];
    float* shX = sm;
    float* shW = sm + CC * PL1;
    int tid = threadIdx.x;
    int coq = tid & 15;
    int lgrp = tid >> 4;
    int b = blockIdx.y;
    int l0 = blockIdx.x * L1T;
    int nrows = NN - l0; if (nrows > L1T + 2) nrows = L1T + 2;

    for (int idx = tid; idx < (L1T + 2) * CC; idx += 256) {
        int l = idx >> 7, ci = idx & (CC - 1);
        shX[ci * PL1 + l] = (l < nrows) ? g_sage[(b * NN + l0 + l) * CC + ci] : 0.f;
    }

    unsigned long long acc[4][8];
    #pragma unroll
    for (int j = 0; j < 4; j++)
        #pragma unroll
        for (int l = 0; l < 8; l++) acc[j][l] = 0ull;

    for (int cc0 = 0; cc0 < CC; cc0 += CI1) {
        __syncthreads();
        for (int idx = tid; idx < CI1 * 3 * CC; idx += 256) {
            shW[idx] = g_w1t[cc0 * 3 * CC + idx];
        }
        __syncthreads();
        #pragma unroll 2
        for (int ci = 0; ci < CI1; ci++) {
            int base = (cc0 + ci) * PL1 + 8 * lgrp;
            unsigned long long xp[10];
            #pragma unroll
            for (int i = 0; i < 10; i++) xp[i] = packdup(shX[base + i]);
            #pragma unroll
            for (int k = 0; k < 3; k++) {
                const ulonglong2* wp = (const ulonglong2*)&shW[(ci * 3 + k) * CC + 8 * coq];
                ulonglong2 w0 = wp[0];
                ulonglong2 w1 = wp[1];
                #pragma unroll
                for (int l = 0; l < 8; l++) {
                    FMA2(acc[0][l], w0.x, xp[l + k]);
                    FMA2(acc[1][l], w0.y, xp[l + k]);
                    FMA2(acc[2][l], w1.x, xp[l + k]);
                    FMA2(acc[3][l], w1.y, xp[l + k]);
                }
            }
        }
    }

    int co0 = 8 * coq;
    float bb[8];
    #pragma unroll
    for (int j = 0; j < 8; j++) bb[j] = b1[co0 + j];
    float mmax[8], mmin[8], msum[8], mssq[8];
    #pragma unroll
    for (int j = 0; j < 8; j++) { mmax[j] = fNINF(); mmin[j] = fPINF(); msum[j] = 0; mssq[j] = 0; }
    int lbase = l0 + 8 * lgrp;
    #pragma unroll
    for (int l = 0; l < 8; l++) {
        if (lbase + l <= NN - 3) {
            float v[8];
            #pragma unroll
            for (int j = 0; j < 4; j++) {
                float2 p = unpack2(acc[j][l]);
                v[2 * j] = p.x + bb[2 * j];
                v[2 * j + 1] = p.y + bb[2 * j + 1];
            }
            #pragma unroll
            for (int j = 0; j < 8; j++) {
                mmax[j] = fmaxf(mmax[j], v[j]);
                mmin[j] = fminf(mmin[j], v[j]);
                msum[j] += v[j];
                mssq[j] += v[j] * v[j];
            }
        }
    }
    #pragma unroll
    for (int j = 0; j < 8; j++) {
        int co = co0 + j;
        atomicAdd(&g_sum1[co], msum[j]);
        atomicAdd(&g_ssq1[co], mssq[j]);
        atomicMaxF(&g_max1[b * CC + co], mmax[j]);
        atomicMinF(&g_min1[b * CC + co], mmin[j]);
    }
}

// ---------------- conv2 via WMMA bf16-split GEMM (mma.sync, works on sm_100) ----------------
// D[co][l] = sum_{kp} A[co][kp] * B[kp][l], kp = ci*4+k (k=3 zero), K'=1024
// Block: 128 co (half h) x 128 l. 8 warps: wy=wid&3 (co 4x32), wx=wid>>2 (l 2x64).
// Warp tile 32co x 64l = 2x4 wmma 16x16 frags. 16 K-chunks of 64.
#define LDA 72
#define LDB 136
#define OFF_X   0        // 130 x 17 floats (8840B, pad to 8960)
#define OFF_AHI 8960     // 128 x LDA bf16 = 18432B
#define OFF_ALO 27392
#define OFF_BHI 45824    // 64 x LDB bf16 = 17408B
#define OFF_BLO 63232
#define SM_CONV2_TOTAL 80640
#define OFF_EP  8960     // epilogue reuse: 8 warps x 32 x 68 floats

__global__ __launch_bounds__(256) void k_conv2(const float* __restrict__ feat,
                                               const float* __restrict__ b2) {
    extern __shared__ char smc[];
    float* shX = (float*)(smc + OFF_X);
    __nv_bfloat16* shAhi = (__nv_bfloat16*)(smc + OFF_AHI);
    __nv_bfloat16* shAlo = (__nv_bfloat16*)(smc + OFF_ALO);
    __nv_bfloat16* shBhi = (__nv_bfloat16*)(smc + OFF_BHI);
    __nv_bfloat16* shBlo = (__nv_bfloat16*)(smc + OFF_BLO);

    int tid = threadIdx.x;
    int wid = tid >> 5, lane = tid & 31;
    int l0 = blockIdx.x * 128;
    int b  = blockIdx.y;
    int h  = blockIdx.z;
    int wy = wid & 3, wx = wid >> 2;

    wmma::fragment<wmma::accumulator, 16, 16, 16, float> facc[2][4];
    #pragma unroll
    for (int i = 0; i < 2; i++)
        #pragma unroll
        for (int j = 0; j < 4; j++) wmma::fill_fragment(facc[i][j], 0.f);

    for (int c = 0; c < 16; c++) {
        __syncthreads();
        // stage X rows l0..l0+129, 16 ci (chunk c)
        int ci0 = c * 16;
        const float* src = (ci0 < CC) ? (g_sage + (size_t)b * NN * CC + ci0)
                                      : (feat + (size_t)b * NN * CC + (ci0 - CC));
        for (int idx = tid; idx < 130 * 4; idx += 256) {
            int row = idx >> 2, f = idx & 3;
            int gr = l0 + row; if (gr > NN - 1) gr = NN - 1;
            float4 v = *(const float4*)(src + (size_t)gr * CC + f * 4);
            int o = row * 17 + f * 4;
            shX[o] = v.x; shX[o + 1] = v.y; shX[o + 2] = v.z; shX[o + 3] = v.w;
        }
        // stage A chunk: co half h, cols c*64..c*64+63 (hi+lo), uint4 = 8 bf16
        for (int idx = tid; idx < 1024; idx += 256) {
            int r = idx >> 3, q = idx & 7;
            int gidx = (h * 128 + r) * 128 + c * 8 + q;
            uint4 vh = g_w2h4[gidx];
            uint4 vl = g_w2l4[gidx];
            *(uint4*)(shAhi + r * LDA + q * 8) = vh;
            *(uint4*)(shAlo + r * LDA + q * 8) = vl;
        }
        __syncthreads();
        // build B[kp][l]: kp local 0..63 -> ci = ci0 + kp/4, k = kp&3
        for (int idx = tid; idx < 64 * 128; idx += 256) {
            int kp = idx >> 7, l = idx & 127;
            int k = kp & 3;
            float v = (k < 3) ? shX[(l + k) * 17 + (kp >> 2)] : 0.f;
            __nv_bfloat16 hi = __float2bfloat16(v);
            __nv_bfloat16 lo = __float2bfloat16(v - __bfloat162float(hi));
            shBhi[kp * LDB + l] = hi;
            shBlo[kp * LDB + l] = lo;
        }
        __syncthreads();
        // mma: 4 k-steps of 16
        #pragma unroll 1
        for (int ks = 0; ks < 4; ks++) {
            wmma::fragment<wmma::matrix_a, 16, 16, 16, __nv_bfloat16, wmma::row_major> fah[2], fal[2];
            wmma::fragment<wmma::matrix_b, 16, 16, 16, __nv_bfloat16, wmma::row_major> fbh[4], fbl[4];
            #pragma unroll
            for (int i = 0; i < 2; i++) {
                const __nv_bfloat16* pa = shAhi + (wy * 32 + i * 16) * LDA + ks * 16;
                wmma::load_matrix_sync(fah[i], pa, LDA);
                wmma::load_matrix_sync(fal[i], pa + (OFF_ALO - OFF_AHI) / 2, LDA);
            }
            #pragma unroll
            for (int j = 0; j < 4; j++) {
                const __nv_bfloat16* pb = shBhi + (ks * 16) * LDB + wx * 64 + j * 16;
                wmma::load_matrix_sync(fbh[j], pb, LDB);
                wmma::load_matrix_sync(fbl[j], pb + (OFF_BLO - OFF_BHI) / 2, LDB);
            }
            #pragma unroll
            for (int i = 0; i < 2; i++)
                #pragma unroll
                for (int j = 0; j < 4; j++) {
                    wmma::mma_sync(facc[i][j], fah[i], fbh[j], facc[i][j]);
                    wmma::mma_sync(facc[i][j], fah[i], fbl[j], facc[i][j]);
                    wmma::mma_sync(facc[i][j], fal[i], fbh[j], facc[i][j]);
                }
        }
    }
    __syncthreads();

    // epilogue: store acc to smem, per-co stats
    float* ep = (float*)(smc + OFF_EP) + wid * (32 * 68);
    #pragma unroll
    for (int i = 0; i < 2; i++)
        #pragma unroll
        for (int j = 0; j < 4; j++)
            wmma::store_matrix_sync(ep + i * 16 * 68 + j * 16, facc[i][j], 68, wmma::mem_row_major);
    __syncwarp();

    {
        int co = h * 128 + wy * 32 + lane;
        float bias = b2[co];
        float mx = fNINF(), mn = fPINF(), s = 0.f, q = 0.f;
        #pragma unroll 4
        for (int l = 0; l < 64; l++) {
            int gl = l0 + wx * 64 + l;
            if (gl <= NN - 3) {
                float v = ep[lane * 68 + l] + bias;
                mx = fmaxf(mx, v); mn = fminf(mn, v);
                s += v; q += v * v;
            }
        }
        atomicAdd(&g_sum2[co], s);
        atomicAdd(&g_ssq2[co], q);
        atomicMaxF(&g_max2[b * C2 + co], mx);
        atomicMinF(&g_min2[b * C2 + co], mn);
    }
}

// ---------------- finish: BN affine + relu + pool + linears + product ----------------
__global__ __launch_bounds__(512) void k_final(const float* __restrict__ g1, const float* __restrict__ be1,
                                               const float* __restrict__ g2, const float* __restrict__ be2,
                                               const float* __restrict__ l1w, const float* __restrict__ l1b,
                                               const float* __restrict__ l2w, const float* __restrict__ l2b,
                                               float* __restrict__ out) {
    __shared__ float p1[BB * CC];
    __shared__ float p2[BB * C2];
    int tid = threadIdx.x;
    const float cnt = (float)(BB * (NN - 2));

    for (int c = tid; c < CC; c += 512) {
        float m = g_sum1[c] / cnt;
        float v = g_ssq1[c] / cnt - m * m;
        float a = g1[c] * rsqrtf(fmaxf(v, 0.f) + 1e-5f);
        float o = be1[c] - a * m;
        for (int b = 0; b < BB; b++) {
            float x = (a >= 0.f) ? g_max1[b * CC + c] : g_min1[b * CC + c];
            p1[b * CC + c] = fmaxf(a * x + o, 0.f);
        }
    }
    for (int c = tid; c < C2; c += 512) {
        float m = g_sum2[c] / cnt;
        float v = g_ssq2[c] / cnt - m * m;
        float a = g2[c] * rsqrtf(fmaxf(v, 0.f) + 1e-5f);
        float o = be2[c] - a * m;
        for (int b = 0; b < BB; b++) {
            float x = (a >= 0.f) ? g_max2[b * C2 + c] : g_min2[b * C2 + c];
            p2[b * C2 + c] = fmaxf(a * x + o, 0.f);
        }
    }
    __syncthreads();
    if (tid < 32) {
        int b = tid >> 1, j = tid & 1;
        float s1 = l1b[j];
        for (int c = 0; c < CC; c++) s1 += p1[b * CC + c] * l1w[j * CC + c];
        float s2 = l2b[j];
        for (int c = 0; c < C2; c++) s2 += p2[b * C2 + c] * l2w[j * C2 + c];
        out[tid] = s1 * s2;
    }
}

// ---------------- host ----------------
extern "C" void kernel_launch(void* const* d_in, const int* in_sizes, int n_in,
                              void* d_out, int out_size) {
    const float* feature = (const float*)d_in[0];
    const void*  topo    = d_in[1];
    const float* lin_l_w = (const float*)d_in[3];
    const float* lin_l_b = (const float*)d_in[4];
    const float* lin_r_w = (const float*)d_in[5];
    const float* conv1_w = (const float*)d_in[6];
    const float* conv1_b = (const float*)d_in[7];
    const float* bn1_g   = (const float*)d_in[8];
    const float* bn1_b   = (const float*)d_in[9];
    const float* conv2_w = (const float*)d_in[10];
    const float* conv2_b = (const float*)d_in[11];
    const float* bn2_g   = (const float*)d_in[12];
    const float* bn2_b   = (const float*)d_in[13];
    const float* lin1_w  = (const float*)d_in[14];
    const float* lin1_b  = (const float*)d_in[15];
    const float* lin2_w  = (const float*)d_in[16];
    const float* lin2_b  = (const float*)d_in[17];
    float* out = (float*)d_out;

    const int SM_SAGE  = (CC * PW * 2 + CC * PA * 2) * 4;
    const int SM_CONV1 = (CC * PL1 + CI1 * 3 * CC) * 4;
    cudaFuncSetAttribute(k_sage,  cudaFuncAttributeMaxDynamicSharedMemorySize, SM_SAGE);
    cudaFuncSetAttribute(k_conv1, cudaFuncAttributeMaxDynamicSharedMemorySize, SM_CONV1);
    cudaFuncSetAttribute(k_conv2, cudaFuncAttributeMaxDynamicSharedMemorySize, SM_CONV2_TOTAL);

    k_detect<<<1, 32>>>((const unsigned int*)topo);
    k_init<<<256, 256>>>();
    k_wprep<<<(CC * 3 * CC + 255) / 256, 256>>>(conv1_w);
    k_wprep2<<<(C2 * 1024) / 256, 256>>>(conv2_w);
    k_hist<<<EDGES / 256, 256>>>(topo);
    k_scan1<<<256, 256>>>();
    k_scan2<<<1, 256>>>();
    k_scan3<<<256, 256>>>();
    k_scatter<<<EDGES / 256, 256>>>(topo);
    k_agg<<<NUM_NODES / 8, 256>>>(feature);
    k_sage<<<NUM_NODES / RPB, 256, SM_SAGE>>>(feature, lin_l_w, lin_l_b, lin_r_w);
    k_conv1<<<dim3(NN / L1T, BB), 256, SM_CONV1>>>(conv1_b);
    k_conv2<<<dim3(NN / 128, BB, 2), 256, SM_CONV2_TOTAL>>>(feature, conv2_b);
    k_final<<<1, 512>>>(bn1_g, bn1_b, bn2_g, bn2_b,
                        lin1_w, lin1_b, lin2_w, lin2_b, out);
}

// round 8
// speedup vs baseline: 2.6307x; 1.4303x over previous
#include <cuda_runtime.h>
#include <cuda_bf16.h>
#include <mma.h>
#include <math.h>

using namespace nvcuda;

#define BB 16
#define NN 4096
#define CC 128
#define C2 256
#define NUM_NODES 65536
#define EDGES 2097152

// ---------------- device scratch (static, no allocs) ----------------
static __device__ int   g_is64;
static __device__ int   g_count[NUM_NODES];
static __device__ int   g_off[NUM_NODES + 1];
static __device__ int   g_cursor[NUM_NODES];
static __device__ int   g_blksum[256];
static __device__ int   g_src[EDGES];
static __device__ float g_agg[NUM_NODES * CC];
static __device__ float g_sage[NUM_NODES * CC];
static __device__ uint4 g_w1h4[CC * 512 / 8];        // conv1 bf16 hi, [co][k'=512]
static __device__ uint4 g_w1l4[CC * 512 / 8];
static __device__ uint4 g_wsh4[CC * 256 / 8];        // sage [Wl|Wr] bf16 hi, [co][k'=256]
static __device__ uint4 g_wsl4[CC * 256 / 8];
static __device__ uint4 g_w2h4[C2 * 1024 / 8];       // conv2 bf16 hi, [co][k'=1024]
static __device__ uint4 g_w2l4[C2 * 1024 / 8];
static __device__ float g_sum1[CC],  g_ssq1[CC];
static __device__ float g_max1[BB * CC], g_min1[BB * CC];
static __device__ float g_sum2[C2],  g_ssq2[C2];
static __device__ float g_max2[BB * C2], g_min2[BB * C2];

__device__ __forceinline__ float fNINF() { return __int_as_float(0xff800000u); }
__device__ __forceinline__ float fPINF() { return __int_as_float(0x7f800000u); }

__device__ __forceinline__ void atomicMaxF(float* a, float v) {
    if (v >= 0.f) atomicMax((int*)a, __float_as_int(v));
    else          atomicMin((unsigned int*)a, __float_as_uint(v));
}
__device__ __forceinline__ void atomicMinF(float* a, float v) {
    if (v >= 0.f) atomicMin((int*)a, __float_as_int(v));
    else          atomicMax((unsigned int*)a, __float_as_uint(v));
}

// ---------------- dtype sniff: int64 vs int32 topo ----------------
__global__ void k_detect(const unsigned int* __restrict__ topo_u32) {
    if (threadIdx.x == 0 && blockIdx.x == 0) {
        int is64 = 1;
        #pragma unroll 1
        for (int i = 0; i < 32; i++) {
            if (topo_u32[2 * i + 1] != 0u) { is64 = 0; break; }
        }
        g_is64 = is64;
    }
}

// ---------------- init scratch (graph-replay safe) ----------------
__global__ void k_init() {
    int i = blockIdx.x * blockDim.x + threadIdx.x;
    if (i < NUM_NODES) g_count[i] = 0;
    if (i < CC) { g_sum1[i] = 0.f; g_ssq1[i] = 0.f; }
    if (i < C2) { g_sum2[i] = 0.f; g_ssq2[i] = 0.f; }
    if (i < BB * CC) { g_max1[i] = fNINF(); g_min1[i] = fPINF(); }
    if (i < BB * C2) { g_max2[i] = fNINF(); g_min2[i] = fPINF(); }
}

// conv1 weights -> bf16 hi/lo, [co][k'=ci*4+k] (k=3 zero)
__global__ void k_wprep1(const float* __restrict__ w1) {
    int i = blockIdx.x * blockDim.x + threadIdx.x;
    if (i >= CC * 512) return;
    int co = i >> 9, kp = i & 511;
    int ci = kp >> 2, k = kp & 3;
    float v = (k < 3) ? w1[co * (CC * 3) + ci * 3 + k] : 0.f;
    __nv_bfloat16 hi = __float2bfloat16(v);
    __nv_bfloat16 lo = __float2bfloat16(v - __bfloat162float(hi));
    ((__nv_bfloat16*)g_w1h4)[i] = hi;
    ((__nv_bfloat16*)g_w1l4)[i] = lo;
}

// sage weights [Wl | Wr] -> bf16 hi/lo, [co][k'=256]
__global__ void k_wpreps(const float* __restrict__ Wl, const float* __restrict__ Wr) {
    int i = blockIdx.x * blockDim.x + threadIdx.x;
    if (i >= CC * 256) return;
    int co = i >> 8, kp = i & 255;
    float v = (kp < CC) ? Wl[co * CC + kp] : Wr[co * CC + (kp - CC)];
    __nv_bfloat16 hi = __float2bfloat16(v);
    __nv_bfloat16 lo = __float2bfloat16(v - __bfloat162float(hi));
    ((__nv_bfloat16*)g_wsh4)[i] = hi;
    ((__nv_bfloat16*)g_wsl4)[i] = lo;
}

// conv2 weights -> bf16 hi/lo, [co][k'=1024] (k=3 zero)
__global__ void k_wprep2(const float* __restrict__ w2) {
    int i = blockIdx.x * blockDim.x + threadIdx.x;
    if (i >= C2 * 1024) return;
    int co = i >> 10, kp = i & 1023;
    int ci = kp >> 2, k = kp & 3;
    float v = (k < 3) ? w2[co * (C2 * 3) + ci * 3 + k] : 0.f;
    __nv_bfloat16 hi = __float2bfloat16(v);
    __nv_bfloat16 lo = __float2bfloat16(v - __bfloat162float(hi));
    ((__nv_bfloat16*)g_w2h4)[i] = hi;
    ((__nv_bfloat16*)g_w2l4)[i] = lo;
}

// ---------------- CSR build ----------------
__global__ void k_hist(const void* __restrict__ topo) {
    int e = blockIdx.x * blockDim.x + threadIdx.x;
    if (e >= EDGES) return;
    int d = g_is64 ? (int)((const long long*)topo)[EDGES + e]
                   : ((const int*)topo)[EDGES + e];
    atomicAdd(&g_count[d], 1);
}

__global__ void k_scan1() {
    __shared__ int sh[256];
    int b = blockIdx.x, t = threadIdx.x;
    int i = b * 256 + t;
    int c = g_count[i];
    sh[t] = c;
    __syncthreads();
    for (int ofs = 1; ofs < 256; ofs <<= 1) {
        int v = (t >= ofs) ? sh[t - ofs] : 0;
        __syncthreads();
        sh[t] += v;
        __syncthreads();
    }
    g_off[i] = sh[t] - c;
    if (t == 255) g_blksum[b] = sh[255];
}

__global__ void k_scan2() {
    __shared__ int sh[256];
    int t = threadIdx.x;
    int c = g_blksum[t];
    sh[t] = c;
    __syncthreads();
    for (int ofs = 1; ofs < 256; ofs <<= 1) {
        int v = (t >= ofs) ? sh[t - ofs] : 0;
        __syncthreads();
        sh[t] += v;
        __syncthreads();
    }
    g_blksum[t] = sh[t] - c;
}

__global__ void k_scan3() {
    int b = blockIdx.x, t = threadIdx.x;
    int i = b * 256 + t;
    int v = g_off[i] + g_blksum[b];
    g_off[i] = v;
    g_cursor[i] = v;
    if (i == NUM_NODES - 1) g_off[NUM_NODES] = EDGES;
}

__global__ void k_scatter(const void* __restrict__ topo) {
    int e = blockIdx.x * blockDim.x + threadIdx.x;
    if (e >= EDGES) return;
    int s, d;
    if (g_is64) {
        s = (int)((const long long*)topo)[e];
        d = (int)((const long long*)topo)[EDGES + e];
    } else {
        s = ((const int*)topo)[e];
        d = ((const int*)topo)[EDGES + e];
    }
    int pos = atomicAdd(&g_cursor[d], 1);
    g_src[pos] = s;
}

// ---------------- per-node max aggregation (warp per node, 4-edge MLP) ----------------
__global__ __launch_bounds__(256) void k_agg(const float* __restrict__ feat) {
    int gwarp = (blockIdx.x * blockDim.x + threadIdx.x) >> 5;
    int lane = threadIdx.x & 31;
    if (gwarp >= NUM_NODES) return;
    int beg = g_off[gwarp], end = g_off[gwarp + 1];
    float4 acc = make_float4(fNINF(), fNINF(), fNINF(), fNINF());
    int i = beg;
    for (; i + 4 <= end; i += 4) {
        int s0 = g_src[i], s1 = g_src[i + 1], s2 = g_src[i + 2], s3 = g_src[i + 3];
        float4 v0 = __ldg(((const float4*)(feat + (size_t)s0 * CC)) + lane);
        float4 v1 = __ldg(((const float4*)(feat + (size_t)s1 * CC)) + lane);
        float4 v2 = __ldg(((const float4*)(feat + (size_t)s2 * CC)) + lane);
        float4 v3 = __ldg(((const float4*)(feat + (size_t)s3 * CC)) + lane);
        float mx = fmaxf(fmaxf(v0.x, v1.x), fmaxf(v2.x, v3.x));
        float my = fmaxf(fmaxf(v0.y, v1.y), fmaxf(v2.y, v3.y));
        float mz = fmaxf(fmaxf(v0.z, v1.z), fmaxf(v2.z, v3.z));
        float mw = fmaxf(fmaxf(v0.w, v1.w), fmaxf(v2.w, v3.w));
        acc.x = fmaxf(acc.x, mx);
        acc.y = fmaxf(acc.y, my);
        acc.z = fmaxf(acc.z, mz);
        acc.w = fmaxf(acc.w, mw);
    }
    for (; i < end; i++) {
        int s0 = g_src[i];
        float4 v0 = __ldg(((const float4*)(feat + (size_t)s0 * CC)) + lane);
        acc.x = fmaxf(acc.x, v0.x);
        acc.y = fmaxf(acc.y, v0.y);
        acc.z = fmaxf(acc.z, v0.z);
        acc.w = fmaxf(acc.w, v0.w);
    }
    if (beg == end) acc = make_float4(0.f, 0.f, 0.f, 0.f);
    ((float4*)(g_agg + (size_t)gwarp * CC))[lane] = acc;
}

// ---------------- sage via WMMA: D[co][node] = [Wl|Wr] @ [agg;feat], bias + L2-norm ----------------
// Block: 128 co x 128 nodes, K'=256 in 4 chunks of 64.
#define SLDA 72
#define SLDB 136
#define SOFF_X   0         // 128 x 65 floats = 33280B
#define SOFF_AH  33280
#define SOFF_AL  51712
#define SOFF_BH  70144
#define SOFF_BL  87552
#define SM_SAGE_TOTAL 104960
__global__ __launch_bounds__(256) void k_sage(const float* __restrict__ feat,
                                              const float* __restrict__ bl) {
    extern __shared__ char smc[];
    float* shX = (float*)(smc + SOFF_X);
    __nv_bfloat16* shAh = (__nv_bfloat16*)(smc + SOFF_AH);
    __nv_bfloat16* shAl = (__nv_bfloat16*)(smc + SOFF_AL);
    __nv_bfloat16* shBh = (__nv_bfloat16*)(smc + SOFF_BH);
    __nv_bfloat16* shBl = (__nv_bfloat16*)(smc + SOFF_BL);

    int tid = threadIdx.x;
    int wid = tid >> 5, lane = tid & 31;
    int n0 = blockIdx.x * 128;
    int wy = wid & 3, wx = wid >> 2;

    wmma::fragment<wmma::accumulator, 16, 16, 16, float> facc[2][4];
    #pragma unroll
    for (int i = 0; i < 2; i++)
        #pragma unroll
        for (int j = 0; j < 4; j++) wmma::fill_fragment(facc[i][j], 0.f);

    for (int c = 0; c < 4; c++) {
        __syncthreads();
        // stage X: 128 nodes x 64 ci (chunk c): c<2 -> agg, else feat
        const float* src = (c < 2) ? (g_agg + (size_t)n0 * CC + c * 64)
                                   : (feat + (size_t)n0 * CC + (c - 2) * 64);
        for (int idx = tid; idx < 128 * 16; idx += 256) {
            int n = idx >> 4, f = idx & 15;
            float4 v = *(const float4*)(src + (size_t)n * CC + f * 4);
            int o = n * 65 + f * 4;
            shX[o] = v.x; shX[o + 1] = v.y; shX[o + 2] = v.z; shX[o + 3] = v.w;
        }
        // stage A: cols c*64..c*64+63 of [co][256]
        for (int idx = tid; idx < 1024; idx += 256) {
            int r = idx >> 3, q = idx & 7;
            int gidx = r * 32 + c * 8 + q;
            *(uint4*)(shAh + r * SLDA + q * 8) = g_wsh4[gidx];
            *(uint4*)(shAl + r * SLDA + q * 8) = g_wsl4[gidx];
        }
        __syncthreads();
        // build B[kp][n] from shX transposed
        for (int idx = tid; idx < 64 * 128; idx += 256) {
            int kp = idx >> 7, n = idx & 127;
            float v = shX[n * 65 + kp];
            __nv_bfloat16 hi = __float2bfloat16(v);
            __nv_bfloat16 lo = __float2bfloat16(v - __bfloat162float(hi));
            shBh[kp * SLDB + n] = hi;
            shBl[kp * SLDB + n] = lo;
        }
        __syncthreads();
        #pragma unroll 1
        for (int ks = 0; ks < 4; ks++) {
            wmma::fragment<wmma::matrix_a, 16, 16, 16, __nv_bfloat16, wmma::row_major> fah[2], fal[2];
            wmma::fragment<wmma::matrix_b, 16, 16, 16, __nv_bfloat16, wmma::row_major> fbh[4], fbl[4];
            #pragma unroll
            for (int i = 0; i < 2; i++) {
                const __nv_bfloat16* pa = shAh + (wy * 32 + i * 16) * SLDA + ks * 16;
                wmma::load_matrix_sync(fah[i], pa, SLDA);
                wmma::load_matrix_sync(fal[i], pa + (SOFF_AL - SOFF_AH) / 2, SLDA);
            }
            #pragma unroll
            for (int j = 0; j < 4; j++) {
                const __nv_bfloat16* pb = shBh + (ks * 16) * SLDB + wx * 64 + j * 16;
                wmma::load_matrix_sync(fbh[j], pb, SLDB);
                wmma::load_matrix_sync(fbl[j], pb + (SOFF_BL - SOFF_BH) / 2, SLDB);
            }
            #pragma unroll
            for (int i = 0; i < 2; i++)
                #pragma unroll
                for (int j = 0; j < 4; j++) {
                    wmma::mma_sync(facc[i][j], fah[i], fbh[j], facc[i][j]);
                    wmma::mma_sync(facc[i][j], fah[i], fbl[j], facc[i][j]);
                    wmma::mma_sync(facc[i][j], fal[i], fbh[j], facc[i][j]);
                }
        }
    }
    __syncthreads();

    // epilogue: ep[co][n] (ld 132), bias -> per-node L2 norm -> write g_sage[node][co]
    float* ep = (float*)smc;
    #pragma unroll
    for (int i = 0; i < 2; i++)
        #pragma unroll
        for (int j = 0; j < 4; j++)
            wmma::store_matrix_sync(ep + (wy * 32 + i * 16) * 132 + wx * 64 + j * 16,
                                    facc[i][j], 132, wmma::mem_row_major);
    __syncthreads();

    if (tid < 128) {
        int n = tid;
        float ss = 0.f;
        #pragma unroll 4
        for (int co = 0; co < CC; co++) {
            float v = ep[co * 132 + n] + bl[co];
            ss += v * v;
        }
        float inv = 1.f / fmaxf(sqrtf(ss), 1e-12f);
        float* dst = g_sage + (size_t)(n0 + n) * CC;
        #pragma unroll 4
        for (int co = 0; co < CC; co += 4) {
            float4 o4;
            o4.x = (ep[(co + 0) * 132 + n] + bl[co + 0]) * inv;
            o4.y = (ep[(co + 1) * 132 + n] + bl[co + 1]) * inv;
            o4.z = (ep[(co + 2) * 132 + n] + bl[co + 2]) * inv;
            o4.w = (ep[(co + 3) * 132 + n] + bl[co + 3]) * inv;
            *(float4*)(dst + co) = o4;
        }
    }
}

// ---------------- conv1 via WMMA: D[128co][128l], K'=512 in 8 chunks ----------------
#define LDA 72
#define LDB 136
#define OFF_X   0        // 130 x 17 floats -> pad 8960
#define OFF_AHI 8960
#define OFF_ALO 27392
#define OFF_BHI 45824
#define OFF_BLO 63232
#define SM_CONVW_TOTAL 80640
#define OFF_EP  8960

__global__ __launch_bounds__(256) void k_conv1(const float* __restrict__ b1) {
    extern __shared__ char smc[];
    float* shX = (float*)(smc + OFF_X);
    __nv_bfloat16* shAhi = (__nv_bfloat16*)(smc + OFF_AHI);
    __nv_bfloat16* shAlo = (__nv_bfloat16*)(smc + OFF_ALO);
    __nv_bfloat16* shBhi = (__nv_bfloat16*)(smc + OFF_BHI);
    __nv_bfloat16* shBlo = (__nv_bfloat16*)(smc + OFF_BLO);

    int tid = threadIdx.x;
    int wid = tid >> 5, lane = tid & 31;
    int l0 = blockIdx.x * 128;
    int b  = blockIdx.y;
    int wy = wid & 3, wx = wid >> 2;

    wmma::fragment<wmma::accumulator, 16, 16, 16, float> facc[2][4];
    #pragma unroll
    for (int i = 0; i < 2; i++)
        #pragma unroll
        for (int j = 0; j < 4; j++) wmma::fill_fragment(facc[i][j], 0.f);

    for (int c = 0; c < 8; c++) {
        __syncthreads();
        int ci0 = c * 16;
        const float* src = g_sage + (size_t)b * NN * CC + ci0;
        for (int idx = tid; idx < 130 * 4; idx += 256) {
            int row = idx >> 2, f = idx & 3;
            int gr = l0 + row; if (gr > NN - 1) gr = NN - 1;
            float4 v = *(const float4*)(src + (size_t)gr * CC + f * 4);
            int o = row * 17 + f * 4;
            shX[o] = v.x; shX[o + 1] = v.y; shX[o + 2] = v.z; shX[o + 3] = v.w;
        }
        for (int idx = tid; idx < 1024; idx += 256) {
            int r = idx >> 3, q = idx & 7;
            int gidx = r * 64 + c * 8 + q;
            *(uint4*)(shAhi + r * LDA + q * 8) = g_w1h4[gidx];
            *(uint4*)(shAlo + r * LDA + q * 8) = g_w1l4[gidx];
        }
        __syncthreads();
        for (int idx = tid; idx < 64 * 128; idx += 256) {
            int kp = idx >> 7, l = idx & 127;
            int k = kp & 3;
            float v = (k < 3) ? shX[(l + k) * 17 + (kp >> 2)] : 0.f;
            __nv_bfloat16 hi = __float2bfloat16(v);
            __nv_bfloat16 lo = __float2bfloat16(v - __bfloat162float(hi));
            shBhi[kp * LDB + l] = hi;
            shBlo[kp * LDB + l] = lo;
        }
        __syncthreads();
        #pragma unroll 1
        for (int ks = 0; ks < 4; ks++) {
            wmma::fragment<wmma::matrix_a, 16, 16, 16, __nv_bfloat16, wmma::row_major> fah[2], fal[2];
            wmma::fragment<wmma::matrix_b, 16, 16, 16, __nv_bfloat16, wmma::row_major> fbh[4], fbl[4];
            #pragma unroll
            for (int i = 0; i < 2; i++) {
                const __nv_bfloat16* pa = shAhi + (wy * 32 + i * 16) * LDA + ks * 16;
                wmma::load_matrix_sync(fah[i], pa, LDA);
                wmma::load_matrix_sync(fal[i], pa + (OFF_ALO - OFF_AHI) / 2, LDA);
            }
            #pragma unroll
            for (int j = 0; j < 4; j++) {
                const __nv_bfloat16* pb = shBhi + (ks * 16) * LDB + wx * 64 + j * 16;
                wmma::load_matrix_sync(fbh[j], pb, LDB);
                wmma::load_matrix_sync(fbl[j], pb + (OFF_BLO - OFF_BHI) / 2, LDB);
            }
            #pragma unroll
            for (int i = 0; i < 2; i++)
                #pragma unroll
                for (int j = 0; j < 4; j++) {
                    wmma::mma_sync(facc[i][j], fah[i], fbh[j], facc[i][j]);
                    wmma::mma_sync(facc[i][j], fah[i], fbl[j], facc[i][j]);
                    wmma::mma_sync(facc[i][j], fal[i], fbh[j], facc[i][j]);
                }
        }
    }
    __syncthreads();

    float* ep = (float*)(smc + OFF_EP) + wid * (32 * 68);
    #pragma unroll
    for (int i = 0; i < 2; i++)
        #pragma unroll
        for (int j = 0; j < 4; j++)
            wmma::store_matrix_sync(ep + i * 16 * 68 + j * 16, facc[i][j], 68, wmma::mem_row_major);
    __syncwarp();

    {
        int co = wy * 32 + lane;
        float bias = b1[co];
        float mx = fNINF(), mn = fPINF(), s = 0.f, q = 0.f;
        #pragma unroll 4
        for (int l = 0; l < 64; l++) {
            int gl = l0 + wx * 64 + l;
            if (gl <= NN - 3) {
                float v = ep[lane * 68 + l] + bias;
                mx = fmaxf(mx, v); mn = fminf(mn, v);
                s += v; q += v * v;
            }
        }
        atomicAdd(&g_sum1[co], s);
        atomicAdd(&g_ssq1[co], q);
        atomicMaxF(&g_max1[b * CC + co], mx);
        atomicMinF(&g_min1[b * CC + co], mn);
    }
}

// ---------------- conv2 via WMMA bf16-split GEMM ----------------
__global__ __launch_bounds__(256) void k_conv2(const float* __restrict__ feat,
                                               const float* __restrict__ b2) {
    extern __shared__ char smc[];
    float* shX = (float*)(smc + OFF_X);
    __nv_bfloat16* shAhi = (__nv_bfloat16*)(smc + OFF_AHI);
    __nv_bfloat16* shAlo = (__nv_bfloat16*)(smc + OFF_ALO);
    __nv_bfloat16* shBhi = (__nv_bfloat16*)(smc + OFF_BHI);
    __nv_bfloat16* shBlo = (__nv_bfloat16*)(smc + OFF_BLO);

    int tid = threadIdx.x;
    int wid = tid >> 5, lane = tid & 31;
    int l0 = blockIdx.x * 128;
    int b  = blockIdx.y;
    int h  = blockIdx.z;
    int wy = wid & 3, wx = wid >> 2;

    wmma::fragment<wmma::accumulator, 16, 16, 16, float> facc[2][4];
    #pragma unroll
    for (int i = 0; i < 2; i++)
        #pragma unroll
        for (int j = 0; j < 4; j++) wmma::fill_fragment(facc[i][j], 0.f);

    for (int c = 0; c < 16; c++) {
        __syncthreads();
        int ci0 = c * 16;
        const float* src = (ci0 < CC) ? (g_sage + (size_t)b * NN * CC + ci0)
                                      : (feat + (size_t)b * NN * CC + (ci0 - CC));
        for (int idx = tid; idx < 130 * 4; idx += 256) {
            int row = idx >> 2, f = idx & 3;
            int gr = l0 + row; if (gr > NN - 1) gr = NN - 1;
            float4 v = *(const float4*)(src + (size_t)gr * CC + f * 4);
            int o = row * 17 + f * 4;
            shX[o] = v.x; shX[o + 1] = v.y; shX[o + 2] = v.z; shX[o + 3] = v.w;
        }
        for (int idx = tid; idx < 1024; idx += 256) {
            int r = idx >> 3, q = idx & 7;
            int gidx = (h * 128 + r) * 128 + c * 8 + q;
            *(uint4*)(shAhi + r * LDA + q * 8) = g_w2h4[gidx];
            *(uint4*)(shAlo + r * LDA + q * 8) = g_w2l4[gidx];
        }
        __syncthreads();
        for (int idx = tid; idx < 64 * 128; idx += 256) {
            int kp = idx >> 7, l = idx & 127;
            int k = kp & 3;
            float v = (k < 3) ? shX[(l + k) * 17 + (kp >> 2)] : 0.f;
            __nv_bfloat16 hi = __float2bfloat16(v);
            __nv_bfloat16 lo = __float2bfloat16(v - __bfloat162float(hi));
            shBhi[kp * LDB + l] = hi;
            shBlo[kp * LDB + l] = lo;
        }
        __syncthreads();
        #pragma unroll 1
        for (int ks = 0; ks < 4; ks++) {
            wmma::fragment<wmma::matrix_a, 16, 16, 16, __nv_bfloat16, wmma::row_major> fah[2], fal[2];
            wmma::fragment<wmma::matrix_b, 16, 16, 16, __nv_bfloat16, wmma::row_major> fbh[4], fbl[4];
            #pragma unroll
            for (int i = 0; i < 2; i++) {
                const __nv_bfloat16* pa = shAhi + (wy * 32 + i * 16) * LDA + ks * 16;
                wmma::load_matrix_sync(fah[i], pa, LDA);
                wmma::load_matrix_sync(fal[i], pa + (OFF_ALO - OFF_AHI) / 2, LDA);
            }
            #pragma unroll
            for (int j = 0; j < 4; j++) {
                const __nv_bfloat16* pb = shBhi + (ks * 16) * LDB + wx * 64 + j * 16;
                wmma::load_matrix_sync(fbh[j], pb, LDB);
                wmma::load_matrix_sync(fbl[j], pb + (OFF_BLO - OFF_BHI) / 2, LDB);
            }
            #pragma unroll
            for (int i = 0; i < 2; i++)
                #pragma unroll
                for (int j = 0; j < 4; j++) {
                    wmma::mma_sync(facc[i][j], fah[i], fbh[j], facc[i][j]);
                    wmma::mma_sync(facc[i][j], fah[i], fbl[j], facc[i][j]);
                    wmma::mma_sync(facc[i][j], fal[i], fbh[j], facc[i][j]);
                }
        }
    }
    __syncthreads();

    float* ep = (float*)(smc + OFF_EP) + wid * (32 * 68);
    #pragma unroll
    for (int i = 0; i < 2; i++)
        #pragma unroll
        for (int j = 0; j < 4; j++)
            wmma::store_matrix_sync(ep + i * 16 * 68 + j * 16, facc[i][j], 68, wmma::mem_row_major);
    __syncwarp();

    {
        int co = h * 128 + wy * 32 + lane;
        float bias = b2[co];
        float mx = fNINF(), mn = fPINF(), s = 0.f, q = 0.f;
        #pragma unroll 4
        for (int l = 0; l < 64; l++) {
            int gl = l0 + wx * 64 + l;
            if (gl <= NN - 3) {
                float v = ep[lane * 68 + l] + bias;
                mx = fmaxf(mx, v); mn = fminf(mn, v);
                s += v; q += v * v;
            }
        }
        atomicAdd(&g_sum2[co], s);
        atomicAdd(&g_ssq2[co], q);
        atomicMaxF(&g_max2[b * C2 + co], mx);
        atomicMinF(&g_min2[b * C2 + co], mn);
    }
}

// ---------------- finish: BN affine + relu + pool + linears + product ----------------
__global__ __launch_bounds__(512) void k_final(const float* __restrict__ g1, const float* __restrict__ be1,
                                               const float* __restrict__ g2, const float* __restrict__ be2,
                                               const float* __restrict__ l1w, const float* __restrict__ l1b,
                                               const float* __restrict__ l2w, const float* __restrict__ l2b,
                                               float* __restrict__ out) {
    __shared__ float p1[BB * CC];
    __shared__ float p2[BB * C2];
    int tid = threadIdx.x;
    const float cnt = (float)(BB * (NN - 2));

    for (int c = tid; c < CC; c += 512) {
        float m = g_sum1[c] / cnt;
        float v = g_ssq1[c] / cnt - m * m;
        float a = g1[c] * rsqrtf(fmaxf(v, 0.f) + 1e-5f);
        float o = be1[c] - a * m;
        for (int b = 0; b < BB; b++) {
            float x = (a >= 0.f) ? g_max1[b * CC + c] : g_min1[b * CC + c];
            p1[b * CC + c] = fmaxf(a * x + o, 0.f);
        }
    }
    for (int c = tid; c < C2; c += 512) {
        float m = g_sum2[c] / cnt;
        float v = g_ssq2[c] / cnt - m * m;
        float a = g2[c] * rsqrtf(fmaxf(v, 0.f) + 1e-5f);
        float o = be2[c] - a * m;
        for (int b = 0; b < BB; b++) {
            float x = (a >= 0.f) ? g_max2[b * C2 + c] : g_min2[b * C2 + c];
            p2[b * C2 + c] = fmaxf(a * x + o, 0.f);
        }
    }
    __syncthreads();
    if (tid < 32) {
        int b = tid >> 1, j = tid & 1;
        float s1 = l1b[j];
        for (int c = 0; c < CC; c++) s1 += p1[b * CC + c] * l1w[j * CC + c];
        float s2 = l2b[j];
        for (int c = 0; c < C2; c++) s2 += p2[b * C2 + c] * l2w[j * C2 + c];
        out[tid] = s1 * s2;
    }
}

// ---------------- host ----------------
extern "C" void kernel_launch(void* const* d_in, const int* in_sizes, int n_in,
                              void* d_out, int out_size) {
    const float* feature = (const float*)d_in[0];
    const void*  topo    = d_in[1];
    const float* lin_l_w = (const float*)d_in[3];
    const float* lin_l_b = (const float*)d_in[4];
    const float* lin_r_w = (const float*)d_in[5];
    const float* conv1_w = (const float*)d_in[6];
    const float* conv1_b = (const float*)d_in[7];
    const float* bn1_g   = (const float*)d_in[8];
    const float* bn1_b   = (const float*)d_in[9];
    const float* conv2_w = (const float*)d_in[10];
    const float* conv2_b = (const float*)d_in[11];
    const float* bn2_g   = (const float*)d_in[12];
    const float* bn2_b   = (const float*)d_in[13];
    const float* lin1_w  = (const float*)d_in[14];
    const float* lin1_b  = (const float*)d_in[15];
    const float* lin2_w  = (const float*)d_in[16];
    const float* lin2_b  = (const float*)d_in[17];
    float* out = (float*)d_out;

    cudaFuncSetAttribute(k_sage,  cudaFuncAttributeMaxDynamicSharedMemorySize, SM_SAGE_TOTAL);
    cudaFuncSetAttribute(k_conv1, cudaFuncAttributeMaxDynamicSharedMemorySize, SM_CONVW_TOTAL);
    cudaFuncSetAttribute(k_conv2, cudaFuncAttributeMaxDynamicSharedMemorySize, SM_CONVW_TOTAL);

    k_detect<<<1, 32>>>((const unsigned int*)topo);
    k_init<<<256, 256>>>();
    k_wprep1<<<(CC * 512) / 256, 256>>>(conv1_w);
    k_wpreps<<<(CC * 256) / 256, 256>>>(lin_l_w, lin_r_w);
    k_wprep2<<<(C2 * 1024) / 256, 256>>>(conv2_w);
    k_hist<<<EDGES / 256, 256>>>(topo);
    k_scan1<<<256, 256>>>();
    k_scan2<<<1, 256>>>();
    k_scan3<<<256, 256>>>();
    k_scatter<<<EDGES / 256, 256>>>(topo);
    k_agg<<<NUM_NODES / 8, 256>>>(feature);
    k_sage<<<NUM_NODES / 128, 256, SM_SAGE_TOTAL>>>(feature, lin_l_b);
    k_conv1<<<dim3(NN / 128, BB), 256, SM_CONVW_TOTAL>>>(conv1_b);
    k_conv2<<<dim3(NN / 128, BB, 2), 256, SM_CONVW_TOTAL>>>(feature, conv2_b);
    k_final<<<1, 512>>>(bn1_g, bn1_b, bn2_g, bn2_b,
                        lin1_w, lin1_b, lin2_w, lin2_b, out);
}

// round 9
// speedup vs baseline: 3.0224x; 1.1489x over previous
#include <cuda_runtime.h>
#include <cuda_bf16.h>
#include <mma.h>
#include <math.h>

using namespace nvcuda;

#define BB 16
#define NN 4096
#define CC 128
#define C2 256
#define NUM_NODES 65536
#define EDGES 2097152

// ---------------- device scratch (static, no allocs) ----------------
static __device__ int   g_is64;
static __device__ int   g_count[NUM_NODES];
static __device__ int   g_off[NUM_NODES + 1];
static __device__ int   g_cursor[NUM_NODES];
static __device__ int   g_blksum[256];
static __device__ int   g_src[EDGES];
static __device__ float g_agg[NUM_NODES * CC];
static __device__ float g_sage[NUM_NODES * CC];
static __device__ uint4 g_w1h4[CC * 384 / 8];        // conv1 bf16 hi, [co][k'=ci*3+k]
static __device__ uint4 g_w1l4[CC * 384 / 8];
static __device__ uint4 g_wsh4[CC * 256 / 8];        // sage [Wl|Wr] bf16 hi, [co][k'=256]
static __device__ uint4 g_wsl4[CC * 256 / 8];
static __device__ uint4 g_w2h4[C2 * 768 / 8];        // conv2 bf16 hi, [co][k'=ci*3+k]
static __device__ uint4 g_w2l4[C2 * 768 / 8];
static __device__ float g_sum1[CC],  g_ssq1[CC];
static __device__ float g_max1[BB * CC], g_min1[BB * CC];
static __device__ float g_sum2[C2],  g_ssq2[C2];
static __device__ float g_max2[BB * C2], g_min2[BB * C2];

__device__ __forceinline__ float fNINF() { return __int_as_float(0xff800000u); }
__device__ __forceinline__ float fPINF() { return __int_as_float(0x7f800000u); }

__device__ __forceinline__ void atomicMaxF(float* a, float v) {
    if (v >= 0.f) atomicMax((int*)a, __float_as_int(v));
    else          atomicMin((unsigned int*)a, __float_as_uint(v));
}
__device__ __forceinline__ void atomicMinF(float* a, float v) {
    if (v >= 0.f) atomicMin((int*)a, __float_as_int(v));
    else          atomicMax((unsigned int*)a, __float_as_uint(v));
}

// ---------------- dtype sniff: int64 vs int32 topo ----------------
__global__ void k_detect(const unsigned int* __restrict__ topo_u32) {
    if (threadIdx.x == 0 && blockIdx.x == 0) {
        int is64 = 1;
        #pragma unroll 1
        for (int i = 0; i < 32; i++) {
            if (topo_u32[2 * i + 1] != 0u) { is64 = 0; break; }
        }
        g_is64 = is64;
    }
}

// ---------------- init scratch (graph-replay safe) ----------------
__global__ void k_init() {
    int i = blockIdx.x * blockDim.x + threadIdx.x;
    if (i < NUM_NODES) g_count[i] = 0;
    if (i < CC) { g_sum1[i] = 0.f; g_ssq1[i] = 0.f; }
    if (i < C2) { g_sum2[i] = 0.f; g_ssq2[i] = 0.f; }
    if (i < BB * CC) { g_max1[i] = fNINF(); g_min1[i] = fPINF(); }
    if (i < BB * C2) { g_max2[i] = fNINF(); g_min2[i] = fPINF(); }
}

// merged weight prep: conv1/conv2 are direct [co][ci*3+k] flattened copies, sage is [Wl|Wr]
__global__ void k_wprep(const float* __restrict__ w1, const float* __restrict__ Wl,
                        const float* __restrict__ Wr, const float* __restrict__ w2) {
    int i = blockIdx.x * blockDim.x + threadIdx.x;
    if (i < CC * 384) {
        float v = w1[i];
        __nv_bfloat16 hi = __float2bfloat16(v);
        __nv_bfloat16 lo = __float2bfloat16(v - __bfloat162float(hi));
        ((__nv_bfloat16*)g_w1h4)[i] = hi;
        ((__nv_bfloat16*)g_w1l4)[i] = lo;
    }
    if (i < CC * 256) {
        int co = i >> 8, kp = i & 255;
        float v = (kp < CC) ? Wl[co * CC + kp] : Wr[co * CC + (kp - CC)];
        __nv_bfloat16 hi = __float2bfloat16(v);
        __nv_bfloat16 lo = __float2bfloat16(v - __bfloat162float(hi));
        ((__nv_bfloat16*)g_wsh4)[i] = hi;
        ((__nv_bfloat16*)g_wsl4)[i] = lo;
    }
    if (i < C2 * 768) {
        float v = w2[i];
        __nv_bfloat16 hi = __float2bfloat16(v);
        __nv_bfloat16 lo = __float2bfloat16(v - __bfloat162float(hi));
        ((__nv_bfloat16*)g_w2h4)[i] = hi;
        ((__nv_bfloat16*)g_w2l4)[i] = lo;
    }
}

// ---------------- CSR build ----------------
__global__ void k_hist(const void* __restrict__ topo) {
    int e = blockIdx.x * blockDim.x + threadIdx.x;
    if (e >= EDGES) return;
    int d = g_is64 ? (int)((const long long*)topo)[EDGES + e]
                   : ((const int*)topo)[EDGES + e];
    atomicAdd(&g_count[d], 1);
}

__global__ void k_scan1() {
    __shared__ int sh[256];
    int b = blockIdx.x, t = threadIdx.x;
    int i = b * 256 + t;
    int c = g_count[i];
    sh[t] = c;
    __syncthreads();
    for (int ofs = 1; ofs < 256; ofs <<= 1) {
        int v = (t >= ofs) ? sh[t - ofs] : 0;
        __syncthreads();
        sh[t] += v;
        __syncthreads();
    }
    g_off[i] = sh[t] - c;
    if (t == 255) g_blksum[b] = sh[255];
}

__global__ void k_scan2() {
    __shared__ int sh[256];
    int t = threadIdx.x;
    int c = g_blksum[t];
    sh[t] = c;
    __syncthreads();
    for (int ofs = 1; ofs < 256; ofs <<= 1) {
        int v = (t >= ofs) ? sh[t - ofs] : 0;
        __syncthreads();
        sh[t] += v;
        __syncthreads();
    }
    g_blksum[t] = sh[t] - c;
}

__global__ void k_scan3() {
    int b = blockIdx.x, t = threadIdx.x;
    int i = b * 256 + t;
    int v = g_off[i] + g_blksum[b];
    g_off[i] = v;
    g_cursor[i] = v;
    if (i == NUM_NODES - 1) g_off[NUM_NODES] = EDGES;
}

__global__ void k_scatter(const void* __restrict__ topo) {
    int e = blockIdx.x * blockDim.x + threadIdx.x;
    if (e >= EDGES) return;
    int s, d;
    if (g_is64) {
        s = (int)((const long long*)topo)[e];
        d = (int)((const long long*)topo)[EDGES + e];
    } else {
        s = ((const int*)topo)[e];
        d = ((const int*)topo)[EDGES + e];
    }
    int pos = atomicAdd(&g_cursor[d], 1);
    g_src[pos] = s;
}

// ---------------- per-node max aggregation (warp per node, 4-edge MLP) ----------------
__global__ __launch_bounds__(256) void k_agg(const float* __restrict__ feat) {
    int gwarp = (blockIdx.x * blockDim.x + threadIdx.x) >> 5;
    int lane = threadIdx.x & 31;
    if (gwarp >= NUM_NODES) return;
    int beg = g_off[gwarp], end = g_off[gwarp + 1];
    float4 acc = make_float4(fNINF(), fNINF(), fNINF(), fNINF());
    int i = beg;
    for (; i + 4 <= end; i += 4) {
        int s0 = g_src[i], s1 = g_src[i + 1], s2 = g_src[i + 2], s3 = g_src[i + 3];
        float4 v0 = __ldg(((const float4*)(feat + (size_t)s0 * CC)) + lane);
        float4 v1 = __ldg(((const float4*)(feat + (size_t)s1 * CC)) + lane);
        float4 v2 = __ldg(((const float4*)(feat + (size_t)s2 * CC)) + lane);
        float4 v3 = __ldg(((const float4*)(feat + (size_t)s3 * CC)) + lane);
        float mx = fmaxf(fmaxf(v0.x, v1.x), fmaxf(v2.x, v3.x));
        float my = fmaxf(fmaxf(v0.y, v1.y), fmaxf(v2.y, v3.y));
        float mz = fmaxf(fmaxf(v0.z, v1.z), fmaxf(v2.z, v3.z));
        float mw = fmaxf(fmaxf(v0.w, v1.w), fmaxf(v2.w, v3.w));
        acc.x = fmaxf(acc.x, mx);
        acc.y = fmaxf(acc.y, my);
        acc.z = fmaxf(acc.z, mz);
        acc.w = fmaxf(acc.w, mw);
    }
    for (; i < end; i++) {
        int s0 = g_src[i];
        float4 v0 = __ldg(((const float4*)(feat + (size_t)s0 * CC)) + lane);
        acc.x = fmaxf(acc.x, v0.x);
        acc.y = fmaxf(acc.y, v0.y);
        acc.z = fmaxf(acc.z, v0.z);
        acc.w = fmaxf(acc.w, v0.w);
    }
    if (beg == end) acc = make_float4(0.f, 0.f, 0.f, 0.f);
    ((float4*)(g_agg + (size_t)gwarp * CC))[lane] = acc;
}

// ---------------- sage via WMMA: D[co][node] = [Wl|Wr] @ [agg;feat], bias + L2-norm ----------------
#define SLDA 72
#define SLDB 136
#define SOFF_X   0         // 128 x 65 floats = 33280B
#define SOFF_AH  33280
#define SOFF_AL  51712
#define SOFF_BH  70144
#define SOFF_BL  87552
#define SM_SAGE_TOTAL 104960
__global__ __launch_bounds__(256) void k_sage(const float* __restrict__ feat,
                                              const float* __restrict__ bl) {
    extern __shared__ char smc[];
    float* shX = (float*)(smc + SOFF_X);
    __nv_bfloat16* shAh = (__nv_bfloat16*)(smc + SOFF_AH);
    __nv_bfloat16* shAl = (__nv_bfloat16*)(smc + SOFF_AL);
    __nv_bfloat16* shBh = (__nv_bfloat16*)(smc + SOFF_BH);
    __nv_bfloat16* shBl = (__nv_bfloat16*)(smc + SOFF_BL);

    int tid = threadIdx.x;
    int wid = tid >> 5;
    int n0 = blockIdx.x * 128;
    int wy = wid & 3, wx = wid >> 2;

    wmma::fragment<wmma::accumulator, 16, 16, 16, float> facc[2][4];
    #pragma unroll
    for (int i = 0; i < 2; i++)
        #pragma unroll
        for (int j = 0; j < 4; j++) wmma::fill_fragment(facc[i][j], 0.f);

    for (int c = 0; c < 4; c++) {
        __syncthreads();
        const float* src = (c < 2) ? (g_agg + (size_t)n0 * CC + c * 64)
                                   : (feat + (size_t)n0 * CC + (c - 2) * 64);
        for (int idx = tid; idx < 128 * 16; idx += 256) {
            int n = idx >> 4, f = idx & 15;
            float4 v = *(const float4*)(src + (size_t)n * CC + f * 4);
            int o = n * 65 + f * 4;
            shX[o] = v.x; shX[o + 1] = v.y; shX[o + 2] = v.z; shX[o + 3] = v.w;
        }
        for (int idx = tid; idx < 1024; idx += 256) {
            int r = idx >> 3, q = idx & 7;
            int gidx = r * 32 + c * 8 + q;
            *(uint4*)(shAh + r * SLDA + q * 8) = g_wsh4[gidx];
            *(uint4*)(shAl + r * SLDA + q * 8) = g_wsl4[gidx];
        }
        __syncthreads();
        for (int idx = tid; idx < 64 * 128; idx += 256) {
            int kp = idx >> 7, n = idx & 127;
            float v = shX[n * 65 + kp];
            __nv_bfloat16 hi = __float2bfloat16(v);
            __nv_bfloat16 lo = __float2bfloat16(v - __bfloat162float(hi));
            shBh[kp * SLDB + n] = hi;
            shBl[kp * SLDB + n] = lo;
        }
        __syncthreads();
        #pragma unroll 1
        for (int ks = 0; ks < 4; ks++) {
            wmma::fragment<wmma::matrix_a, 16, 16, 16, __nv_bfloat16, wmma::row_major> fah[2], fal[2];
            wmma::fragment<wmma::matrix_b, 16, 16, 16, __nv_bfloat16, wmma::row_major> fbh[4], fbl[4];
            #pragma unroll
            for (int i = 0; i < 2; i++) {
                const __nv_bfloat16* pa = shAh + (wy * 32 + i * 16) * SLDA + ks * 16;
                wmma::load_matrix_sync(fah[i], pa, SLDA);
                wmma::load_matrix_sync(fal[i], pa + (SOFF_AL - SOFF_AH) / 2, SLDA);
            }
            #pragma unroll
            for (int j = 0; j < 4; j++) {
                const __nv_bfloat16* pb = shBh + (ks * 16) * SLDB + wx * 64 + j * 16;
                wmma::load_matrix_sync(fbh[j], pb, SLDB);
                wmma::load_matrix_sync(fbl[j], pb + (SOFF_BL - SOFF_BH) / 2, SLDB);
            }
            #pragma unroll
            for (int i = 0; i < 2; i++)
                #pragma unroll
                for (int j = 0; j < 4; j++) {
                    wmma::mma_sync(facc[i][j], fah[i], fbh[j], facc[i][j]);
                    wmma::mma_sync(facc[i][j], fah[i], fbl[j], facc[i][j]);
                    wmma::mma_sync(facc[i][j], fal[i], fbh[j], facc[i][j]);
                }
        }
    }
    __syncthreads();

    float* ep = (float*)smc;
    #pragma unroll
    for (int i = 0; i < 2; i++)
        #pragma unroll
        for (int j = 0; j < 4; j++)
            wmma::store_matrix_sync(ep + (wy * 32 + i * 16) * 132 + wx * 64 + j * 16,
                                    facc[i][j], 132, wmma::mem_row_major);
    __syncthreads();

    if (tid < 128) {
        int n = tid;
        float ss = 0.f;
        #pragma unroll 4
        for (int co = 0; co < CC; co++) {
            float v = ep[co * 132 + n] + bl[co];
            ss += v * v;
        }
        float inv = 1.f / fmaxf(sqrtf(ss), 1e-12f);
        float* dst = g_sage + (size_t)(n0 + n) * CC;
        #pragma unroll 4
        for (int co = 0; co < CC; co += 4) {
            float4 o4;
            o4.x = (ep[(co + 0) * 132 + n] + bl[co + 0]) * inv;
            o4.y = (ep[(co + 1) * 132 + n] + bl[co + 1]) * inv;
            o4.z = (ep[(co + 2) * 132 + n] + bl[co + 2]) * inv;
            o4.w = (ep[(co + 3) * 132 + n] + bl[co + 3]) * inv;
            *(float4*)(dst + co) = o4;
        }
    }
}

// ---------------- conv kernels via WMMA, K' = ci*3+k (no padding) ----------------
// chunk = 16 ci = 48 kp; ks-loop = 3 steps of 16.
#define LDA 56
#define LDB 136
#define OFF_X   0        // 130 x 17 floats -> pad 8960
#define OFF_AHI 8960     // 128 x LDA bf16 = 14336B
#define OFF_ALO 23296
#define OFF_BHI 37632    // 48 x LDB bf16 = 13056B
#define OFF_BLO 50688
#define SM_CONVW_TOTAL 78592
#define OFF_EP  8960     // epilogue: 8 warps x 32 x 68 floats = 69632B (8960+69632=78592)

__global__ __launch_bounds__(256) void k_conv1(const float* __restrict__ b1) {
    extern __shared__ char smc[];
    float* shX = (float*)(smc + OFF_X);
    __nv_bfloat16* shAhi = (__nv_bfloat16*)(smc + OFF_AHI);
    __nv_bfloat16* shAlo = (__nv_bfloat16*)(smc + OFF_ALO);
    __nv_bfloat16* shBhi = (__nv_bfloat16*)(smc + OFF_BHI);
    __nv_bfloat16* shBlo = (__nv_bfloat16*)(smc + OFF_BLO);

    int tid = threadIdx.x;
    int wid = tid >> 5, lane = tid & 31;
    int l0 = blockIdx.x * 128;
    int b  = blockIdx.y;
    int wy = wid & 3, wx = wid >> 2;

    wmma::fragment<wmma::accumulator, 16, 16, 16, float> facc[2][4];
    #pragma unroll
    for (int i = 0; i < 2; i++)
        #pragma unroll
        for (int j = 0; j < 4; j++) wmma::fill_fragment(facc[i][j], 0.f);

    for (int c = 0; c < 8; c++) {
        __syncthreads();
        int ci0 = c * 16;
        const float* src = g_sage + (size_t)b * NN * CC + ci0;
        for (int idx = tid; idx < 130 * 4; idx += 256) {
            int row = idx >> 2, f = idx & 3;
            int gr = l0 + row; if (gr > NN - 1) gr = NN - 1;
            float4 v = *(const float4*)(src + (size_t)gr * CC + f * 4);
            int o = row * 17 + f * 4;
            shX[o] = v.x; shX[o + 1] = v.y; shX[o + 2] = v.z; shX[o + 3] = v.w;
        }
        // A: rows 128 co, 6 uint4 per row (48 bf16), chunk offset c*6 in [co][48 uint4]
        for (int idx = tid; idx < 768; idx += 256) {
            int r = idx / 6, q = idx - r * 6;
            int gidx = r * 48 + c * 6 + q;
            *(uint4*)(shAhi + r * LDA + q * 8) = g_w1h4[gidx];
            *(uint4*)(shAlo + r * LDA + q * 8) = g_w1l4[gidx];
        }
        __syncthreads();
        // B[kp][l], kp = ci_loc*3 + k
        for (int idx = tid; idx < 48 * 128; idx += 256) {
            int kp = idx >> 7, l = idx & 127;
            int ci = kp / 3, k = kp - ci * 3;
            float v = shX[(l + k) * 17 + ci];
            __nv_bfloat16 hi = __float2bfloat16(v);
            __nv_bfloat16 lo = __float2bfloat16(v - __bfloat162float(hi));
            shBhi[kp * LDB + l] = hi;
            shBlo[kp * LDB + l] = lo;
        }
        __syncthreads();
        #pragma unroll 1
        for (int ks = 0; ks < 3; ks++) {
            wmma::fragment<wmma::matrix_a, 16, 16, 16, __nv_bfloat16, wmma::row_major> fah[2], fal[2];
            wmma::fragment<wmma::matrix_b, 16, 16, 16, __nv_bfloat16, wmma::row_major> fbh[4], fbl[4];
            #pragma unroll
            for (int i = 0; i < 2; i++) {
                const __nv_bfloat16* pa = shAhi + (wy * 32 + i * 16) * LDA + ks * 16;
                wmma::load_matrix_sync(fah[i], pa, LDA);
                wmma::load_matrix_sync(fal[i], pa + (OFF_ALO - OFF_AHI) / 2, LDA);
            }
            #pragma unroll
            for (int j = 0; j < 4; j++) {
                const __nv_bfloat16* pb = shBhi + (ks * 16) * LDB + wx * 64 + j * 16;
                wmma::load_matrix_sync(fbh[j], pb, LDB);
                wmma::load_matrix_sync(fbl[j], pb + (OFF_BLO - OFF_BHI) / 2, LDB);
            }
            #pragma unroll
            for (int i = 0; i < 2; i++)
                #pragma unroll
                for (int j = 0; j < 4; j++) {
                    wmma::mma_sync(facc[i][j], fah[i], fbh[j], facc[i][j]);
                    wmma::mma_sync(facc[i][j], fah[i], fbl[j], facc[i][j]);
                    wmma::mma_sync(facc[i][j], fal[i], fbh[j], facc[i][j]);
                }
        }
    }
    __syncthreads();

    float* ep = (float*)(smc + OFF_EP) + wid * (32 * 68);
    #pragma unroll
    for (int i = 0; i < 2; i++)
        #pragma unroll
        for (int j = 0; j < 4; j++)
            wmma::store_matrix_sync(ep + i * 16 * 68 + j * 16, facc[i][j], 68, wmma::mem_row_major);
    __syncwarp();

    {
        int co = wy * 32 + lane;
        float bias = b1[co];
        float mx = fNINF(), mn = fPINF(), s = 0.f, q = 0.f;
        #pragma unroll 4
        for (int l = 0; l < 64; l++) {
            int gl = l0 + wx * 64 + l;
            if (gl <= NN - 3) {
                float v = ep[lane * 68 + l] + bias;
                mx = fmaxf(mx, v); mn = fminf(mn, v);
                s += v; q += v * v;
            }
        }
        atomicAdd(&g_sum1[co], s);
        atomicAdd(&g_ssq1[co], q);
        atomicMaxF(&g_max1[b * CC + co], mx);
        atomicMinF(&g_min1[b * CC + co], mn);
    }
}

__global__ __launch_bounds__(256) void k_conv2(const float* __restrict__ feat,
                                               const float* __restrict__ b2) {
    extern __shared__ char smc[];
    float* shX = (float*)(smc + OFF_X);
    __nv_bfloat16* shAhi = (__nv_bfloat16*)(smc + OFF_AHI);
    __nv_bfloat16* shAlo = (__nv_bfloat16*)(smc + OFF_ALO);
    __nv_bfloat16* shBhi = (__nv_bfloat16*)(smc + OFF_BHI);
    __nv_bfloat16* shBlo = (__nv_bfloat16*)(smc + OFF_BLO);

    int tid = threadIdx.x;
    int wid = tid >> 5, lane = tid & 31;
    int l0 = blockIdx.x * 128;
    int b  = blockIdx.y;
    int h  = blockIdx.z;
    int wy = wid & 3, wx = wid >> 2;

    wmma::fragment<wmma::accumulator, 16, 16, 16, float> facc[2][4];
    #pragma unroll
    for (int i = 0; i < 2; i++)
        #pragma unroll
        for (int j = 0; j < 4; j++) wmma::fill_fragment(facc[i][j], 0.f);

    for (int c = 0; c < 16; c++) {
        __syncthreads();
        int ci0 = c * 16;
        const float* src = (ci0 < CC) ? (g_sage + (size_t)b * NN * CC + ci0)
                                      : (feat + (size_t)b * NN * CC + (ci0 - CC));
        for (int idx = tid; idx < 130 * 4; idx += 256) {
            int row = idx >> 2, f = idx & 3;
            int gr = l0 + row; if (gr > NN - 1) gr = NN - 1;
            float4 v = *(const float4*)(src + (size_t)gr * CC + f * 4);
            int o = row * 17 + f * 4;
            shX[o] = v.x; shX[o + 1] = v.y; shX[o + 2] = v.z; shX[o + 3] = v.w;
        }
        for (int idx = tid; idx < 768; idx += 256) {
            int r = idx / 6, q = idx - r * 6;
            int gidx = (h * 128 + r) * 96 + c * 6 + q;
            *(uint4*)(shAhi + r * LDA + q * 8) = g_w2h4[gidx];
            *(uint4*)(shAlo + r * LDA + q * 8) = g_w2l4[gidx];
        }
        __syncthreads();
        for (int idx = tid; idx < 48 * 128; idx += 256) {
            int kp = idx >> 7, l = idx & 127;
            int ci = kp / 3, k = kp - ci * 3;
            float v = shX[(l + k) * 17 + ci];
            __nv_bfloat16 hi = __float2bfloat16(v);
            __nv_bfloat16 lo = __float2bfloat16(v - __bfloat162float(hi));
            shBhi[kp * LDB + l] = hi;
            shBlo[kp * LDB + l] = lo;
        }
        __syncthreads();
        #pragma unroll 1
        for (int ks = 0; ks < 3; ks++) {
            wmma::fragment<wmma::matrix_a, 16, 16, 16, __nv_bfloat16, wmma::row_major> fah[2], fal[2];
            wmma::fragment<wmma::matrix_b, 16, 16, 16, __nv_bfloat16, wmma::row_major> fbh[4], fbl[4];
            #pragma unroll
            for (int i = 0; i < 2; i++) {
                const __nv_bfloat16* pa = shAhi + (wy * 32 + i * 16) * LDA + ks * 16;
                wmma::load_matrix_sync(fah[i], pa, LDA);
                wmma::load_matrix_sync(fal[i], pa + (OFF_ALO - OFF_AHI) / 2, LDA);
            }
            #pragma unroll
            for (int j = 0; j < 4; j++) {
                const __nv_bfloat16* pb = shBhi + (ks * 16) * LDB + wx * 64 + j * 16;
                wmma::load_matrix_sync(fbh[j], pb, LDB);
                wmma::load_matrix_sync(fbl[j], pb + (OFF_BLO - OFF_BHI) / 2, LDB);
            }
            #pragma unroll
            for (int i = 0; i < 2; i++)
                #pragma unroll
                for (int j = 0; j < 4; j++) {
                    wmma::mma_sync(facc[i][j], fah[i], fbh[j], facc[i][j]);
                    wmma::mma_sync(facc[i][j], fah[i], fbl[j], facc[i][j]);
                    wmma::mma_sync(facc[i][j], fal[i], fbh[j], facc[i][j]);
                }
        }
    }
    __syncthreads();

    float* ep = (float*)(smc + OFF_EP) + wid * (32 * 68);
    #pragma unroll
    for (int i = 0; i < 2; i++)
        #pragma unroll
        for (int j = 0; j < 4; j++)
            wmma::store_matrix_sync(ep + i * 16 * 68 + j * 16, facc[i][j], 68, wmma::mem_row_major);
    __syncwarp();

    {
        int co = h * 128 + wy * 32 + lane;
        float bias = b2[co];
        float mx = fNINF(), mn = fPINF(), s = 0.f, q = 0.f;
        #pragma unroll 4
        for (int l = 0; l < 64; l++) {
            int gl = l0 + wx * 64 + l;
            if (gl <= NN - 3) {
                float v = ep[lane * 68 + l] + bias;
                mx = fmaxf(mx, v); mn = fminf(mn, v);
                s += v; q += v * v;
            }
        }
        atomicAdd(&g_sum2[co], s);
        atomicAdd(&g_ssq2[co], q);
        atomicMaxF(&g_max2[b * C2 + co], mx);
        atomicMinF(&g_min2[b * C2 + co], mn);
    }
}

// ---------------- finish: BN affine + relu + pool + linears + product ----------------
__global__ __launch_bounds__(512) void k_final(const float* __restrict__ g1, const float* __restrict__ be1,
                                               const float* __restrict__ g2, const float* __restrict__ be2,
                                               const float* __restrict__ l1w, const float* __restrict__ l1b,
                                               const float* __restrict__ l2w, const float* __restrict__ l2b,
                                               float* __restrict__ out) {
    __shared__ float p1[BB * CC];
    __shared__ float p2[BB * C2];
    int tid = threadIdx.x;
    const float cnt = (float)(BB * (NN - 2));

    for (int c = tid; c < CC; c += 512) {
        float m = g_sum1[c] / cnt;
        float v = g_ssq1[c] / cnt - m * m;
        float a = g1[c] * rsqrtf(fmaxf(v, 0.f) + 1e-5f);
        float o = be1[c] - a * m;
        for (int b = 0; b < BB; b++) {
            float x = (a >= 0.f) ? g_max1[b * CC + c] : g_min1[b * CC + c];
            p1[b * CC + c] = fmaxf(a * x + o, 0.f);
        }
    }
    for (int c = tid; c < C2; c += 512) {
        float m = g_sum2[c] / cnt;
        float v = g_ssq2[c] / cnt - m * m;
        float a = g2[c] * rsqrtf(fmaxf(v, 0.f) + 1e-5f);
        float o = be2[c] - a * m;
        for (int b = 0; b < BB; b++) {
            float x = (a >= 0.f) ? g_max2[b * C2 + c] : g_min2[b * C2 + c];
            p2[b * C2 + c] = fmaxf(a * x + o, 0.f);
        }
    }
    __syncthreads();
    if (tid < 32) {
        int b = tid >> 1, j = tid & 1;
        float s1 = l1b[j];
        for (int c = 0; c < CC; c++) s1 += p1[b * CC + c] * l1w[j * CC + c];
        float s2 = l2b[j];
        for (int c = 0; c < C2; c++) s2 += p2[b * C2 + c] * l2w[j * C2 + c];
        out[tid] = s1 * s2;
    }
}

// ---------------- host ----------------
extern "C" void kernel_launch(void* const* d_in, const int* in_sizes, int n_in,
                              void* d_out, int out_size) {
    const float* feature = (const float*)d_in[0];
    const void*  topo    = d_in[1];
    const float* lin_l_w = (const float*)d_in[3];
    const float* lin_l_b = (const float*)d_in[4];
    const float* lin_r_w = (const float*)d_in[5];
    const float* conv1_w = (const float*)d_in[6];
    const float* conv1_b = (const float*)d_in[7];
    const float* bn1_g   = (const float*)d_in[8];
    const float* bn1_b   = (const float*)d_in[9];
    const float* conv2_w = (const float*)d_in[10];
    const float* conv2_b = (const float*)d_in[11];
    const float* bn2_g   = (const float*)d_in[12];
    const float* bn2_b   = (const float*)d_in[13];
    const float* lin1_w  = (const float*)d_in[14];
    const float* lin1_b  = (const float*)d_in[15];
    const float* lin2_w  = (const float*)d_in[16];
    const float* lin2_b  = (const float*)d_in[17];
    float* out = (float*)d_out;

    cudaFuncSetAttribute(k_sage,  cudaFuncAttributeMaxDynamicSharedMemorySize, SM_SAGE_TOTAL);
    cudaFuncSetAttribute(k_conv1, cudaFuncAttributeMaxDynamicSharedMemorySize, SM_CONVW_TOTAL);
    cudaFuncSetAttribute(k_conv2, cudaFuncAttributeMaxDynamicSharedMemorySize, SM_CONVW_TOTAL);

    k_detect<<<1, 32>>>((const unsigned int*)topo);
    k_init<<<256, 256>>>();
    k_wprep<<<(C2 * 768) / 256, 256>>>(conv1_w, lin_l_w, lin_r_w, conv2_w);
    k_hist<<<EDGES / 256, 256>>>(topo);
    k_scan1<<<256, 256>>>();
    k_scan2<<<1, 256>>>();
    k_scan3<<<256, 256>>>();
    k_scatter<<<EDGES / 256, 256>>>(topo);
    k_agg<<<NUM_NODES / 8, 256>>>(feature);
    k_sage<<<NUM_NODES / 128, 256, SM_SAGE_TOTAL>>>(feature, lin_l_b);
    k_conv1<<<dim3(NN / 128, BB), 256, SM_CONVW_TOTAL>>>(conv1_b);
    k_conv2<<<dim3(NN / 128, BB, 2), 256, SM_CONVW_TOTAL>>>(feature, conv2_b);
    k_final<<<1, 512>>>(bn1_g, bn1_b, bn2_g, bn2_b,
                        lin1_w, lin1_b, lin2_w, lin2_b, out);
}